// round 8
// baseline (speedup 1.0000x reference)
#include <cuda_runtime.h>
#include <math.h>
#include <cstdint>

#define EDIM 1024
#define NH   16
#define HD   64
#define BB   2
#define SS   2048
#define MTOT (BB*SS)   // 4096

// Scratch
__device__ float g_Q[MTOT*EDIM];
__device__ float g_K[MTOT*EDIM];
__device__ float g_V[MTOT*EDIM];
__device__ float g_ctx[MTOT*EDIM];
__device__ float g_Wt[4][EDIM*EDIM];   // transposed weights [n][k]

__device__ __forceinline__ uint32_t cvt_tf32(float x) {
    uint32_t r; asm("cvt.rna.tf32.f32 %0, %1;" : "=r"(r) : "f"(x));
    return r;
}

__device__ __forceinline__ void mma_tf32(float& d0, float& d1, float& d2, float& d3,
                                         uint32_t a0, uint32_t a1, uint32_t a2, uint32_t a3,
                                         uint32_t b0, uint32_t b1) {
    asm volatile(
        "mma.sync.aligned.m16n8k8.row.col.f32.tf32.tf32.f32 "
        "{%0,%1,%2,%3},{%4,%5,%6,%7},{%8,%9},{%0,%1,%2,%3};"
        : "+f"(d0), "+f"(d1), "+f"(d2), "+f"(d3)
        : "r"(a0), "r"(a1), "r"(a2), "r"(a3), "r"(b0), "r"(b1));
}

// ============================ fused transpose (grid.z selects W) ============================
__global__ __launch_bounds__(256)
void transpose4(const float* __restrict__ w0, const float* __restrict__ w1,
                const float* __restrict__ w2, const float* __restrict__ w3)
{
    const float* in = (blockIdx.z == 0) ? w0 : (blockIdx.z == 1) ? w1 : (blockIdx.z == 2) ? w2 : w3;
    float* out = g_Wt[blockIdx.z];
    __shared__ float t[32][33];
    int x = blockIdx.x * 32 + threadIdx.x;
    int y = blockIdx.y * 32 + threadIdx.y;
#pragma unroll
    for (int j = 0; j < 32; j += 8)
        t[threadIdx.y + j][threadIdx.x] = in[(size_t)(y + j) * EDIM + x];
    __syncthreads();
    x = blockIdx.y * 32 + threadIdx.x;
    y = blockIdx.x * 32 + threadIdx.y;
#pragma unroll
    for (int j = 0; j < 32; j += 8)
        out[(size_t)(y + j) * EDIM + x] = t[threadIdx.x][threadIdx.y + j];
}

// ============================ tf32 mma.sync GEMM ============================
#define GBM 128
#define GBN 128
#define GBK 32
#define LDP 36
#define TILE_U32 (128 * LDP)

struct GemmSmem { uint32_t a[2][TILE_U32]; uint32_t b[2][TILE_U32]; };

__device__ __forceinline__ void gemm_body(const float* __restrict__ A, const float* __restrict__ Wt,
                                          const float* __restrict__ bias, float* __restrict__ C,
                                          int head_layout, uint32_t* sm, int m0, int n0)
{
    uint32_t* As[2] = { sm,                sm + 2 * TILE_U32 };
    uint32_t* Bs[2] = { sm + TILE_U32,     sm + 3 * TILE_U32 };

    const int tid = threadIdx.x;
    const int wid = tid >> 5;
    const int lane = tid & 31;
    const int warp_m = (wid & 3) * 32;
    const int warp_n = (wid >> 2) * 64;
    const int r4 = lane >> 2;
    const int c4 = lane & 3;

    float acc[2][8][4];
#pragma unroll
    for (int mt = 0; mt < 2; mt++)
#pragma unroll
        for (int nt = 0; nt < 8; nt++)
#pragma unroll
            for (int i = 0; i < 4; i++) acc[mt][nt][i] = 0.f;

    const int sr = tid >> 1;
    const int sc = (tid & 1) * 16;
    auto stage = [&](int buf, int k0) {
        uint32_t* Ad = As[buf];
        uint32_t* Bd = Bs[buf];
#pragma unroll
        for (int i = 0; i < 4; i++) {
            float4 v = *reinterpret_cast<const float4*>(&A[(size_t)(m0 + sr) * EDIM + k0 + sc + i * 4]);
            uint32_t* p = &Ad[sr * LDP + sc + i * 4];
            p[0] = cvt_tf32(v.x); p[1] = cvt_tf32(v.y); p[2] = cvt_tf32(v.z); p[3] = cvt_tf32(v.w);
        }
#pragma unroll
        for (int i = 0; i < 4; i++) {
            float4 v = *reinterpret_cast<const float4*>(&Wt[(size_t)(n0 + sr) * EDIM + k0 + sc + i * 4]);
            uint32_t* p = &Bd[sr * LDP + sc + i * 4];
            p[0] = cvt_tf32(v.x); p[1] = cvt_tf32(v.y); p[2] = cvt_tf32(v.z); p[3] = cvt_tf32(v.w);
        }
    };

    stage(0, 0);
    __syncthreads();

    const int NCHUNK = EDIM / GBK;
    for (int c = 0; c < NCHUNK; c++) {
        const int cur = c & 1;
        if (c + 1 < NCHUNK) stage(cur ^ 1, (c + 1) * GBK);

        const uint32_t* Ab = As[cur];
        const uint32_t* Bb = Bs[cur];
#pragma unroll
        for (int ks = 0; ks < 4; ks++) {
            const int kb = ks * 8;
            uint32_t af[2][4];
#pragma unroll
            for (int mt = 0; mt < 2; mt++) {
                const uint32_t* base = &Ab[(warp_m + mt * 16 + r4) * LDP + kb + c4];
                af[mt][0] = base[0];
                af[mt][1] = base[8 * LDP];
                af[mt][2] = base[4];
                af[mt][3] = base[8 * LDP + 4];
            }
            uint32_t bf[8][2];
#pragma unroll
            for (int nt = 0; nt < 8; nt++) {
                const uint32_t* base = &Bb[(warp_n + nt * 8 + r4) * LDP + kb + c4];
                bf[nt][0] = base[0];
                bf[nt][1] = base[4];
            }
#pragma unroll
            for (int mt = 0; mt < 2; mt++)
#pragma unroll
                for (int nt = 0; nt < 8; nt++)
                    mma_tf32(acc[mt][nt][0], acc[mt][nt][1], acc[mt][nt][2], acc[mt][nt][3],
                             af[mt][0], af[mt][1], af[mt][2], af[mt][3],
                             bf[nt][0], bf[nt][1]);
        }
        __syncthreads();
    }

#pragma unroll
    for (int mt = 0; mt < 2; mt++) {
#pragma unroll
        for (int half = 0; half < 2; half++) {
            const int m = m0 + warp_m + mt * 16 + r4 + half * 8;
            const int b_ = m >> 11;
            const int s_ = m & (SS - 1);
#pragma unroll
            for (int nt = 0; nt < 8; nt++) {
                const int col = n0 + warp_n + nt * 8 + 2 * c4;
                float2 o;
                o.x = acc[mt][nt][half * 2 + 0] + bias[col];
                o.y = acc[mt][nt][half * 2 + 1] + bias[col + 1];
                if (head_layout) {
                    const int h = col >> 6;
                    const int d = col & (HD - 1);
                    *reinterpret_cast<float2*>(
                        &C[(((size_t)(b_ * NH + h) * SS + s_) * HD) + d]) = o;
                } else {
                    *reinterpret_cast<float2*>(&C[(size_t)m * EDIM + col]) = o;
                }
            }
        }
    }
}

// fused QKV projection: grid.z in {0,1,2} picks weight/bias/output
__global__ __launch_bounds__(256)
void gemm_qkv(const float* __restrict__ X,
              const float* __restrict__ bq, const float* __restrict__ bk,
              const float* __restrict__ bv)
{
    extern __shared__ uint32_t sm[];
    const int z = blockIdx.z;
    const float* Wt = g_Wt[z];
    const float* bias = (z == 0) ? bq : (z == 1) ? bk : bv;
    float* C = (z == 0) ? g_Q : (z == 1) ? g_K : g_V;
    gemm_body(X, Wt, bias, C, 1, sm, blockIdx.x * GBM, blockIdx.y * GBN);
}

__global__ __launch_bounds__(256)
void gemm_out(const float* __restrict__ bo, float* __restrict__ C)
{
    extern __shared__ uint32_t sm[];
    gemm_body(g_ctx, g_Wt[3], bo, C, 0, sm, blockIdx.x * GBM, blockIdx.y * GBN);
}

// ============================ flash attention with mma.sync tf32 ============================
// CTA: 128 q rows of one (b,h); 8 warps x 16 rows. KV tiles of 64.
#define LKK 68
#define LVV 72
#define LPP 68
#define AOFF_V  (64 * LKK)                 // 4352
#define AOFF_P  (AOFF_V + 64 * LVV)        // 8960
#define AOFF_MD (AOFF_P + 8 * 16 * LPP)    // 17664
#define ATT_SMEM ((AOFF_MD + 64) * 4)      // 70912 bytes

__global__ __launch_bounds__(256)
void attn_mma(const float* __restrict__ mask)
{
    extern __shared__ uint32_t sm[];
    uint32_t* Ks = sm;
    uint32_t* Vs = sm + AOFF_V;
    float*    madd = reinterpret_cast<float*>(sm + AOFF_MD);

    const int bh = blockIdx.y;
    const int b_ = bh >> 4;
    const int h  = bh & (NH - 1);
    const int q0 = blockIdx.x * 128;
    const int tid = threadIdx.x;
    const int wid = tid >> 5;
    const int lane = tid & 31;
    const int r4 = lane >> 2;
    const int c4 = lane & 3;
    uint32_t* Pw = sm + AOFF_P + wid * 16 * LPP;

    const int qrow = q0 + wid * 16;   // warp's first query row (within S)

    // Q fragments in registers for entire KV loop
    uint32_t aq[8][4];
    {
        const float* Qb = g_Q + ((size_t)bh * SS + qrow) * HD;
#pragma unroll
        for (int ks = 0; ks < 8; ks++) {
            aq[ks][0] = cvt_tf32(Qb[(size_t)r4 * HD + ks * 8 + c4]);
            aq[ks][1] = cvt_tf32(Qb[(size_t)(r4 + 8) * HD + ks * 8 + c4]);
            aq[ks][2] = cvt_tf32(Qb[(size_t)r4 * HD + ks * 8 + c4 + 4]);
            aq[ks][3] = cvt_tf32(Qb[(size_t)(r4 + 8) * HD + ks * 8 + c4 + 4]);
        }
    }

    float ctx[8][4];
#pragma unroll
    for (int nt = 0; nt < 8; nt++)
#pragma unroll
        for (int i = 0; i < 4; i++) ctx[nt][i] = 0.f;
    float m0 = -1e30f, m1 = -1e30f, l0 = 0.f, l1 = 0.f;
    const float scale = 0.125f;

    const int krow = tid >> 2;
    const int kcb = (tid & 3) * 16;

    for (int kt = 0; kt < SS; kt += 64) {
        __syncthreads();
        // stage K [key][d] and V [key][d], tf32
        {
            const float* Kp = g_K + ((size_t)bh * SS + kt + krow) * HD + kcb;
            const float* Vp = g_V + ((size_t)bh * SS + kt + krow) * HD + kcb;
#pragma unroll
            for (int i = 0; i < 4; i++) {
                float4 v = *reinterpret_cast<const float4*>(&Kp[i * 4]);
                uint32_t* p = &Ks[krow * LKK + kcb + i * 4];
                p[0] = cvt_tf32(v.x); p[1] = cvt_tf32(v.y); p[2] = cvt_tf32(v.z); p[3] = cvt_tf32(v.w);
            }
#pragma unroll
            for (int i = 0; i < 4; i++) {
                float4 v = *reinterpret_cast<const float4*>(&Vp[i * 4]);
                uint32_t* p = &Vs[krow * LVV + kcb + i * 4];
                p[0] = cvt_tf32(v.x); p[1] = cvt_tf32(v.y); p[2] = cvt_tf32(v.z); p[3] = cvt_tf32(v.w);
            }
            if (tid < 64)
                madd[tid] = (1.0f - mask[b_ * SS + kt + tid]) * -10000.0f;
        }
        __syncthreads();

        // ---- S = Q @ K^T ----
        float sf[8][4];
#pragma unroll
        for (int nt = 0; nt < 8; nt++) {
            sf[nt][0] = sf[nt][1] = sf[nt][2] = sf[nt][3] = 0.f;
#pragma unroll
            for (int ks = 0; ks < 8; ks++) {
                const uint32_t* base = &Ks[(nt * 8 + r4) * LKK + ks * 8 + c4];
                mma_tf32(sf[nt][0], sf[nt][1], sf[nt][2], sf[nt][3],
                         aq[ks][0], aq[ks][1], aq[ks][2], aq[ks][3],
                         base[0], base[4]);
            }
        }

        // ---- scale + mask + online softmax ----
        float rm0 = -1e30f, rm1 = -1e30f;
#pragma unroll
        for (int nt = 0; nt < 8; nt++) {
            float ma = madd[nt * 8 + 2 * c4];
            float mb = madd[nt * 8 + 2 * c4 + 1];
            sf[nt][0] = sf[nt][0] * scale + ma;
            sf[nt][1] = sf[nt][1] * scale + mb;
            sf[nt][2] = sf[nt][2] * scale + ma;
            sf[nt][3] = sf[nt][3] * scale + mb;
            rm0 = fmaxf(rm0, fmaxf(sf[nt][0], sf[nt][1]));
            rm1 = fmaxf(rm1, fmaxf(sf[nt][2], sf[nt][3]));
        }
        rm0 = fmaxf(rm0, __shfl_xor_sync(0xffffffff, rm0, 1));
        rm0 = fmaxf(rm0, __shfl_xor_sync(0xffffffff, rm0, 2));
        rm1 = fmaxf(rm1, __shfl_xor_sync(0xffffffff, rm1, 1));
        rm1 = fmaxf(rm1, __shfl_xor_sync(0xffffffff, rm1, 2));

        float nm0 = fmaxf(m0, rm0), nm1 = fmaxf(m1, rm1);
        float corr0 = __expf(m0 - nm0), corr1 = __expf(m1 - nm1);
        m0 = nm0; m1 = nm1;

        float rs0 = 0.f, rs1 = 0.f;
#pragma unroll
        for (int nt = 0; nt < 8; nt++) {
            sf[nt][0] = __expf(sf[nt][0] - nm0);
            sf[nt][1] = __expf(sf[nt][1] - nm0);
            sf[nt][2] = __expf(sf[nt][2] - nm1);
            sf[nt][3] = __expf(sf[nt][3] - nm1);
            rs0 += sf[nt][0] + sf[nt][1];
            rs1 += sf[nt][2] + sf[nt][3];
        }
        rs0 += __shfl_xor_sync(0xffffffff, rs0, 1);
        rs0 += __shfl_xor_sync(0xffffffff, rs0, 2);
        rs1 += __shfl_xor_sync(0xffffffff, rs1, 1);
        rs1 += __shfl_xor_sync(0xffffffff, rs1, 2);
        l0 = l0 * corr0 + rs0;
        l1 = l1 * corr1 + rs1;

#pragma unroll
        for (int nt = 0; nt < 8; nt++) {
            ctx[nt][0] *= corr0; ctx[nt][1] *= corr0;
            ctx[nt][2] *= corr1; ctx[nt][3] *= corr1;
        }

        // ---- store P (tf32) to warp-private SMEM ----
#pragma unroll
        for (int nt = 0; nt < 8; nt++) {
            uint2 lo = make_uint2(cvt_tf32(sf[nt][0]), cvt_tf32(sf[nt][1]));
            uint2 hi = make_uint2(cvt_tf32(sf[nt][2]), cvt_tf32(sf[nt][3]));
            *reinterpret_cast<uint2*>(&Pw[r4 * LPP + nt * 8 + 2 * c4]) = lo;
            *reinterpret_cast<uint2*>(&Pw[(r4 + 8) * LPP + nt * 8 + 2 * c4]) = hi;
        }
        __syncwarp();

        // ---- ctx += P @ V ----
#pragma unroll
        for (int ks2 = 0; ks2 < 8; ks2++) {
            uint32_t ap0 = Pw[r4 * LPP + ks2 * 8 + c4];
            uint32_t ap1 = Pw[(r4 + 8) * LPP + ks2 * 8 + c4];
            uint32_t ap2 = Pw[r4 * LPP + ks2 * 8 + c4 + 4];
            uint32_t ap3 = Pw[(r4 + 8) * LPP + ks2 * 8 + c4 + 4];
#pragma unroll
            for (int nt2 = 0; nt2 < 8; nt2++) {
                uint32_t b0 = Vs[(ks2 * 8 + c4) * LVV + nt2 * 8 + r4];
                uint32_t b1 = Vs[(ks2 * 8 + c4 + 4) * LVV + nt2 * 8 + r4];
                mma_tf32(ctx[nt2][0], ctx[nt2][1], ctx[nt2][2], ctx[nt2][3],
                         ap0, ap1, ap2, ap3, b0, b1);
            }
        }
        __syncwarp();
    }

    // ---- epilogue: normalize, write to g_ctx [B,S,E] ----
    float inv0 = 1.0f / l0;
    float inv1 = 1.0f / l1;
    const int sq0 = qrow + r4;
    float* C0 = g_ctx + ((size_t)(b_ * SS + sq0) * EDIM) + h * HD;
    float* C1 = g_ctx + ((size_t)(b_ * SS + sq0 + 8) * EDIM) + h * HD;
#pragma unroll
    for (int nt2 = 0; nt2 < 8; nt2++) {
        const int col = nt2 * 8 + 2 * c4;
        *reinterpret_cast<float2*>(&C0[col]) = make_float2(ctx[nt2][0] * inv0, ctx[nt2][1] * inv0);
        *reinterpret_cast<float2*>(&C1[col]) = make_float2(ctx[nt2][2] * inv1, ctx[nt2][3] * inv1);
    }
}

// ============================ launch ============================
extern "C" void kernel_launch(void* const* d_in, const int* in_sizes, int n_in,
                              void* d_out, int out_size)
{
    const float* X    = (const float*)d_in[0];
    const float* mask = (const float*)d_in[1];
    const float* Wq   = (const float*)d_in[2];
    const float* bq   = (const float*)d_in[3];
    const float* Wk   = (const float*)d_in[4];
    const float* bk   = (const float*)d_in[5];
    const float* Wv   = (const float*)d_in[6];
    const float* bv   = (const float*)d_in[7];
    const float* Wo   = (const float*)d_in[8];
    const float* bo   = (const float*)d_in[9];
    float* out = (float*)d_out;

    const int gemm_smem = 4 * TILE_U32 * 4;   // 73728
    cudaFuncSetAttribute(gemm_qkv, cudaFuncAttributeMaxDynamicSharedMemorySize, gemm_smem);
    cudaFuncSetAttribute(gemm_out, cudaFuncAttributeMaxDynamicSharedMemorySize, gemm_smem);
    cudaFuncSetAttribute(attn_mma, cudaFuncAttributeMaxDynamicSharedMemorySize, ATT_SMEM);

    dim3 tgrid(32, 32, 4), tblk(32, 8);
    transpose4<<<tgrid, tblk>>>(Wq, Wk, Wv, Wo);

    dim3 qkvgrid(MTOT / GBM, EDIM / GBN, 3);   // 32 x 8 x 3
    gemm_qkv<<<qkvgrid, 256, gemm_smem>>>(X, bq, bk, bv);

    dim3 agrid(SS / 128, BB * NH);             // 16 x 32
    attn_mma<<<agrid, 256, ATT_SMEM>>>(mask);

    dim3 ogrid(MTOT / GBM, EDIM / GBN);        // 32 x 8
    gemm_out<<<ogrid, 256, gemm_smem>>>(bo, out);
}

// round 9
// speedup vs baseline: 1.2032x; 1.2032x over previous
#include <cuda_runtime.h>
#include <math.h>
#include <cstdint>

#define EDIM 1024
#define NH   16
#define HD   64
#define BB   2
#define SS   2048
#define MTOT (BB*SS)   // 4096

// Scratch (tf32 bit patterns stored as uint32)
__device__ uint32_t g_Xt[MTOT*EDIM];
__device__ uint32_t g_Q[MTOT*EDIM];
__device__ uint32_t g_K[MTOT*EDIM];
__device__ uint32_t g_V[MTOT*EDIM];
__device__ uint32_t g_ctx[MTOT*EDIM];
__device__ uint32_t g_Wt[4][EDIM*EDIM];   // transposed weights [n][k], tf32 bits

__device__ __forceinline__ uint32_t cvt_tf32(float x) {
    uint32_t r; asm("cvt.rna.tf32.f32 %0, %1;" : "=r"(r) : "f"(x));
    return r;
}
__device__ __forceinline__ void mma_tf32(float& d0, float& d1, float& d2, float& d3,
                                         uint32_t a0, uint32_t a1, uint32_t a2, uint32_t a3,
                                         uint32_t b0, uint32_t b1) {
    asm volatile(
        "mma.sync.aligned.m16n8k8.row.col.f32.tf32.tf32.f32 "
        "{%0,%1,%2,%3},{%4,%5,%6,%7},{%8,%9},{%0,%1,%2,%3};"
        : "+f"(d0), "+f"(d1), "+f"(d2), "+f"(d3)
        : "r"(a0), "r"(a1), "r"(a2), "r"(a3), "r"(b0), "r"(b1));
}
__device__ __forceinline__ void ldsm4(uint32_t& r0, uint32_t& r1, uint32_t& r2, uint32_t& r3,
                                      uint32_t addr) {
    asm volatile("ldmatrix.sync.aligned.m8n8.x4.shared.b16 {%0,%1,%2,%3}, [%4];"
                 : "=r"(r0), "=r"(r1), "=r"(r2), "=r"(r3) : "r"(addr));
}
__device__ __forceinline__ void cp16(uint32_t dst, const void* src) {
    asm volatile("cp.async.cg.shared.global [%0], [%1], 16;" :: "r"(dst), "l"(src));
}
__device__ __forceinline__ void cp_commit() { asm volatile("cp.async.commit_group;"); }
__device__ __forceinline__ void cp_wait0()  { asm volatile("cp.async.wait_group 0;" ::: "memory"); }

// ============================ X -> tf32 prep ============================
__global__ __launch_bounds__(256)
void prep_x(const float* __restrict__ X)
{
    size_t i = ((size_t)blockIdx.x * 256 + threadIdx.x) * 4;
    float4 v = *reinterpret_cast<const float4*>(&X[i]);
    uint4 o;
    o.x = cvt_tf32(v.x); o.y = cvt_tf32(v.y); o.z = cvt_tf32(v.z); o.w = cvt_tf32(v.w);
    *reinterpret_cast<uint4*>(&g_Xt[i]) = o;
}

// ============================ fused transpose (tf32 out) ============================
__global__ __launch_bounds__(256)
void transpose4(const float* __restrict__ w0, const float* __restrict__ w1,
                const float* __restrict__ w2, const float* __restrict__ w3)
{
    const float* in = (blockIdx.z == 0) ? w0 : (blockIdx.z == 1) ? w1 : (blockIdx.z == 2) ? w2 : w3;
    uint32_t* out = g_Wt[blockIdx.z];
    __shared__ float t[32][33];
    int x = blockIdx.x * 32 + threadIdx.x;
    int y = blockIdx.y * 32 + threadIdx.y;
#pragma unroll
    for (int j = 0; j < 32; j += 8)
        t[threadIdx.y + j][threadIdx.x] = in[(size_t)(y + j) * EDIM + x];
    __syncthreads();
    x = blockIdx.y * 32 + threadIdx.x;
    y = blockIdx.x * 32 + threadIdx.y;
#pragma unroll
    for (int j = 0; j < 32; j += 8)
        out[(size_t)(y + j) * EDIM + x] = cvt_tf32(t[threadIdx.x][threadIdx.y + j]);
}

// ============================ tf32 mma.sync GEMM ============================
#define GBM 128
#define GBN 128
#define GBK 32
#define LDP 36
#define TILE_U32 (128 * LDP)

__device__ __forceinline__ void gemm_body(const uint32_t* __restrict__ A,
                                          const uint32_t* __restrict__ Wt,
                                          const float* __restrict__ bias,
                                          void* __restrict__ Cv,
                                          int tf32_head_out, int m0, int n0)
{
    extern __shared__ uint32_t sm[];
    const uint32_t sb = (uint32_t)__cvta_generic_to_shared(sm);

    const int tid = threadIdx.x;
    const int wid = tid >> 5;
    const int lane = tid & 31;
    const int warp_m = (wid & 3) * 32;
    const int warp_n = (wid >> 2) * 64;
    const int r4 = lane >> 2;
    const int c4 = lane & 3;
    const int quad = lane >> 3;
    const int lrow = lane & 7;

    float acc[2][8][4];
#pragma unroll
    for (int mt = 0; mt < 2; mt++)
#pragma unroll
        for (int nt = 0; nt < 8; nt++)
#pragma unroll
            for (int i = 0; i < 4; i++) acc[mt][nt][i] = 0.f;

    const int sr = tid >> 1;
    const int sc = (tid & 1) * 16;
    auto stage = [&](int buf, int k0) {
        uint32_t ad = sb + (uint32_t)((buf * 2 * TILE_U32 + sr * LDP + sc) * 4);
        const uint32_t* Ap = &A[(size_t)(m0 + sr) * EDIM + k0 + sc];
#pragma unroll
        for (int i = 0; i < 4; i++) cp16(ad + i * 16, Ap + i * 4);
        uint32_t bd = sb + (uint32_t)(((buf * 2 + 1) * TILE_U32 + sr * LDP + sc) * 4);
        const uint32_t* Bp = &Wt[(size_t)(n0 + sr) * EDIM + k0 + sc];
#pragma unroll
        for (int i = 0; i < 4; i++) cp16(bd + i * 16, Bp + i * 4);
    };

    const uint32_t aoff = (uint32_t)(((warp_m + (quad & 1) * 8 + lrow) * LDP + (quad >> 1) * 4) * 4);
    const uint32_t boff = (uint32_t)(((warp_n + (quad >> 1) * 8 + lrow) * LDP + (quad & 1) * 4) * 4);

    stage(0, 0);
    cp_commit();

    const int NCHUNK = EDIM / GBK;   // 32
    for (int c = 0; c < NCHUNK; c++) {
        const int cur = c & 1;
        cp_wait0();
        __syncthreads();
        if (c + 1 < NCHUNK) { stage(cur ^ 1, (c + 1) * GBK); cp_commit(); }

        const uint32_t ab = sb + (uint32_t)(cur * 2 * TILE_U32 * 4);
        const uint32_t bb = sb + (uint32_t)((cur * 2 + 1) * TILE_U32 * 4);
#pragma unroll
        for (int ks = 0; ks < 4; ks++) {
            const uint32_t kbb = (uint32_t)(ks * 32);   // ks*8 u32 -> bytes
            uint32_t af[2][4];
#pragma unroll
            for (int mt = 0; mt < 2; mt++)
                ldsm4(af[mt][0], af[mt][1], af[mt][2], af[mt][3],
                      ab + aoff + (uint32_t)(mt * 16 * LDP * 4) + kbb);
            uint32_t bf[8][2];
#pragma unroll
            for (int p = 0; p < 4; p++)
                ldsm4(bf[2 * p][0], bf[2 * p][1], bf[2 * p + 1][0], bf[2 * p + 1][1],
                      bb + boff + (uint32_t)(p * 16 * LDP * 4) + kbb);
#pragma unroll
            for (int mt = 0; mt < 2; mt++)
#pragma unroll
                for (int nt = 0; nt < 8; nt++)
                    mma_tf32(acc[mt][nt][0], acc[mt][nt][1], acc[mt][nt][2], acc[mt][nt][3],
                             af[mt][0], af[mt][1], af[mt][2], af[mt][3],
                             bf[nt][0], bf[nt][1]);
        }
    }

    // ---- epilogue ----
#pragma unroll
    for (int mt = 0; mt < 2; mt++) {
#pragma unroll
        for (int half = 0; half < 2; half++) {
            const int m = m0 + warp_m + mt * 16 + r4 + half * 8;
            const int b_ = m >> 11;
            const int s_ = m & (SS - 1);
#pragma unroll
            for (int nt = 0; nt < 8; nt++) {
                const int col = warp_n + n0 + nt * 8 + 2 * c4;
                float ox = acc[mt][nt][half * 2 + 0] + bias[col];
                float oy = acc[mt][nt][half * 2 + 1] + bias[col + 1];
                if (tf32_head_out) {
                    const int h = col >> 6;
                    const int d = col & (HD - 1);
                    uint32_t* C = (uint32_t*)Cv;
                    *reinterpret_cast<uint2*>(
                        &C[(((size_t)(b_ * NH + h) * SS + s_) * HD) + d]) =
                        make_uint2(cvt_tf32(ox), cvt_tf32(oy));
                } else {
                    float* C = (float*)Cv;
                    *reinterpret_cast<float2*>(&C[(size_t)m * EDIM + col]) = make_float2(ox, oy);
                }
            }
        }
    }
}

__global__ __launch_bounds__(256)
void gemm_qkv(const float* __restrict__ bq, const float* __restrict__ bk,
              const float* __restrict__ bv)
{
    const int z = blockIdx.z;
    const float* bias = (z == 0) ? bq : (z == 1) ? bk : bv;
    uint32_t* C = (z == 0) ? g_Q : (z == 1) ? g_K : g_V;
    gemm_body(g_Xt, g_Wt[z], bias, C, 1, blockIdx.x * GBM, blockIdx.y * GBN);
}

__global__ __launch_bounds__(256)
void gemm_out(const float* __restrict__ bo, float* __restrict__ C)
{
    gemm_body(g_ctx, g_Wt[3], bo, C, 0, blockIdx.x * GBM, blockIdx.y * GBN);
}

// ============================ flash attention, ldmatrix + cp.async ============================
#define LKK 68
#define LVV 72
#define LPP 68
#define OFF_K0 0
#define OFF_V0 (64 * LKK)                  // 4352
#define OFF_K1 (OFF_V0 + 64 * LVV)         // 8960
#define OFF_V1 (OFF_K1 + 64 * LKK)         // 13312
#define OFF_P  (OFF_V1 + 64 * LVV)         // 17920
#define OFF_MD (OFF_P + 8 * 16 * LPP)      // 26624
#define ATT_SMEM ((OFF_MD + 128) * 4)      // 107008 bytes

__global__ __launch_bounds__(256)
void attn_mma(const float* __restrict__ mask)
{
    extern __shared__ uint32_t sm[];
    const uint32_t sb = (uint32_t)__cvta_generic_to_shared(sm);
    float* madds = reinterpret_cast<float*>(sm + OFF_MD);

    const int bh = blockIdx.y;
    const int b_ = bh >> 4;
    const int h  = bh & (NH - 1);
    const int q0 = blockIdx.x * 128;
    const int tid = threadIdx.x;
    const int wid = tid >> 5;
    const int lane = tid & 31;
    const int r4 = lane >> 2;
    const int c4 = lane & 3;
    const int quad = lane >> 3;
    const int lrow = lane & 7;

    const int ks_off[2] = { OFF_K0, OFF_K1 };
    const int vs_off[2] = { OFF_V0, OFF_V1 };
    const int qrow = q0 + wid * 16;

    // Q fragments (raw tf32 bits) in registers for entire KV loop
    uint32_t aq[8][4];
    {
        const uint32_t* Qb = g_Q + ((size_t)bh * SS + qrow) * HD;
#pragma unroll
        for (int ks = 0; ks < 8; ks++) {
            aq[ks][0] = Qb[(size_t)r4 * HD + ks * 8 + c4];
            aq[ks][1] = Qb[(size_t)(r4 + 8) * HD + ks * 8 + c4];
            aq[ks][2] = Qb[(size_t)r4 * HD + ks * 8 + c4 + 4];
            aq[ks][3] = Qb[(size_t)(r4 + 8) * HD + ks * 8 + c4 + 4];
        }
    }

    float ctx[8][4];
#pragma unroll
    for (int nt = 0; nt < 8; nt++)
#pragma unroll
        for (int i = 0; i < 4; i++) ctx[nt][i] = 0.f;
    float m0 = -1e30f, m1 = -1e30f, l0 = 0.f, l1 = 0.f;
    const float scale = 0.125f;

    const int krow = tid >> 2;
    const int kcb = (tid & 3) * 16;

    auto stage = [&](int buf, int kt) {
        const uint32_t* Kp = g_K + ((size_t)bh * SS + kt + krow) * HD + kcb;
        const uint32_t* Vp = g_V + ((size_t)bh * SS + kt + krow) * HD + kcb;
        uint32_t kd = sb + (uint32_t)((ks_off[buf] + krow * LKK + kcb) * 4);
        uint32_t vd = sb + (uint32_t)((vs_off[buf] + krow * LVV + kcb) * 4);
#pragma unroll
        for (int i = 0; i < 4; i++) cp16(kd + i * 16, Kp + i * 4);
#pragma unroll
        for (int i = 0; i < 4; i++) cp16(vd + i * 16, Vp + i * 4);
        if (tid < 64)
            madds[buf * 64 + tid] = (1.0f - mask[b_ * SS + kt + tid]) * -10000.0f;
    };

    // ldmatrix lane offsets
    const uint32_t koff = (uint32_t)((((quad >> 1) * 8 + lrow) * LKK + (quad & 1) * 4) * 4);
    const uint32_t poff = (uint32_t)((((quad & 1) * 8 + lrow) * LPP + (quad >> 1) * 4) * 4);
    const uint32_t pwbase = sb + (uint32_t)((OFF_P + wid * 16 * LPP) * 4);
    uint32_t* Pw = sm + OFF_P + wid * 16 * LPP;

    stage(0, 0);
    cp_commit();

    const int NT = SS / 64;   // 32
    for (int t = 0; t < NT; t++) {
        const int cur = t & 1;
        cp_wait0();
        __syncthreads();
        if (t + 1 < NT) { stage(cur ^ 1, (t + 1) * 64); cp_commit(); }

        const uint32_t kb = sb + (uint32_t)(ks_off[cur] * 4);
        const float* madd = &madds[cur * 64];

        // ---- S = Q @ K^T ----
        float sf[8][4];
#pragma unroll
        for (int nt = 0; nt < 8; nt++)
            sf[nt][0] = sf[nt][1] = sf[nt][2] = sf[nt][3] = 0.f;
#pragma unroll
        for (int ks = 0; ks < 8; ks++) {
            uint32_t bf[8][2];
#pragma unroll
            for (int p = 0; p < 4; p++)
                ldsm4(bf[2 * p][0], bf[2 * p][1], bf[2 * p + 1][0], bf[2 * p + 1][1],
                      kb + koff + (uint32_t)(p * 16 * LKK * 4) + (uint32_t)(ks * 32));
#pragma unroll
            for (int nt = 0; nt < 8; nt++)
                mma_tf32(sf[nt][0], sf[nt][1], sf[nt][2], sf[nt][3],
                         aq[ks][0], aq[ks][1], aq[ks][2], aq[ks][3],
                         bf[nt][0], bf[nt][1]);
        }

        // ---- scale + mask + online softmax ----
        float rm0 = -1e30f, rm1 = -1e30f;
#pragma unroll
        for (int nt = 0; nt < 8; nt++) {
            float ma = madd[nt * 8 + 2 * c4];
            float mb = madd[nt * 8 + 2 * c4 + 1];
            sf[nt][0] = sf[nt][0] * scale + ma;
            sf[nt][1] = sf[nt][1] * scale + mb;
            sf[nt][2] = sf[nt][2] * scale + ma;
            sf[nt][3] = sf[nt][3] * scale + mb;
            rm0 = fmaxf(rm0, fmaxf(sf[nt][0], sf[nt][1]));
            rm1 = fmaxf(rm1, fmaxf(sf[nt][2], sf[nt][3]));
        }
        rm0 = fmaxf(rm0, __shfl_xor_sync(0xffffffff, rm0, 1));
        rm0 = fmaxf(rm0, __shfl_xor_sync(0xffffffff, rm0, 2));
        rm1 = fmaxf(rm1, __shfl_xor_sync(0xffffffff, rm1, 1));
        rm1 = fmaxf(rm1, __shfl_xor_sync(0xffffffff, rm1, 2));

        float nm0 = fmaxf(m0, rm0), nm1 = fmaxf(m1, rm1);
        float corr0 = __expf(m0 - nm0), corr1 = __expf(m1 - nm1);
        m0 = nm0; m1 = nm1;

        float rs0 = 0.f, rs1 = 0.f;
#pragma unroll
        for (int nt = 0; nt < 8; nt++) {
            sf[nt][0] = __expf(sf[nt][0] - nm0);
            sf[nt][1] = __expf(sf[nt][1] - nm0);
            sf[nt][2] = __expf(sf[nt][2] - nm1);
            sf[nt][3] = __expf(sf[nt][3] - nm1);
            rs0 += sf[nt][0] + sf[nt][1];
            rs1 += sf[nt][2] + sf[nt][3];
        }
        rs0 += __shfl_xor_sync(0xffffffff, rs0, 1);
        rs0 += __shfl_xor_sync(0xffffffff, rs0, 2);
        rs1 += __shfl_xor_sync(0xffffffff, rs1, 1);
        rs1 += __shfl_xor_sync(0xffffffff, rs1, 2);
        l0 = l0 * corr0 + rs0;
        l1 = l1 * corr1 + rs1;

#pragma unroll
        for (int nt = 0; nt < 8; nt++) {
            ctx[nt][0] *= corr0; ctx[nt][1] *= corr0;
            ctx[nt][2] *= corr1; ctx[nt][3] *= corr1;
        }

        // ---- store P (tf32) to warp-private SMEM ----
#pragma unroll
        for (int nt = 0; nt < 8; nt++) {
            uint2 lo = make_uint2(cvt_tf32(sf[nt][0]), cvt_tf32(sf[nt][1]));
            uint2 hi = make_uint2(cvt_tf32(sf[nt][2]), cvt_tf32(sf[nt][3]));
            *reinterpret_cast<uint2*>(&Pw[r4 * LPP + nt * 8 + 2 * c4]) = lo;
            *reinterpret_cast<uint2*>(&Pw[(r4 + 8) * LPP + nt * 8 + 2 * c4]) = hi;
        }
        __syncwarp();

        // ---- ctx += P @ V ----
        const uint32_t* Vsp = sm + vs_off[cur];
#pragma unroll
        for (int ks2 = 0; ks2 < 8; ks2++) {
            uint32_t ap0, ap1, ap2, ap3;
            ldsm4(ap0, ap1, ap2, ap3, pwbase + poff + (uint32_t)(ks2 * 32));
#pragma unroll
            for (int nt2 = 0; nt2 < 8; nt2++) {
                uint32_t b0 = Vsp[(ks2 * 8 + c4) * LVV + nt2 * 8 + r4];
                uint32_t b1 = Vsp[(ks2 * 8 + c4 + 4) * LVV + nt2 * 8 + r4];
                mma_tf32(ctx[nt2][0], ctx[nt2][1], ctx[nt2][2], ctx[nt2][3],
                         ap0, ap1, ap2, ap3, b0, b1);
            }
        }
        __syncwarp();
    }

    // ---- epilogue: normalize, write tf32 bits to g_ctx [B,S,E] ----
    float inv0 = 1.0f / l0;
    float inv1 = 1.0f / l1;
    const int sq0 = qrow + r4;
    uint32_t* C0 = g_ctx + ((size_t)(b_ * SS + sq0) * EDIM) + h * HD;
    uint32_t* C1 = g_ctx + ((size_t)(b_ * SS + sq0 + 8) * EDIM) + h * HD;
#pragma unroll
    for (int nt2 = 0; nt2 < 8; nt2++) {
        const int col = nt2 * 8 + 2 * c4;
        *reinterpret_cast<uint2*>(&C0[col]) =
            make_uint2(cvt_tf32(ctx[nt2][0] * inv0), cvt_tf32(ctx[nt2][1] * inv0));
        *reinterpret_cast<uint2*>(&C1[col]) =
            make_uint2(cvt_tf32(ctx[nt2][2] * inv1), cvt_tf32(ctx[nt2][3] * inv1));
    }
}

// ============================ launch ============================
extern "C" void kernel_launch(void* const* d_in, const int* in_sizes, int n_in,
                              void* d_out, int out_size)
{
    const float* X    = (const float*)d_in[0];
    const float* mask = (const float*)d_in[1];
    const float* Wq   = (const float*)d_in[2];
    const float* bq   = (const float*)d_in[3];
    const float* Wk   = (const float*)d_in[4];
    const float* bk   = (const float*)d_in[5];
    const float* Wv   = (const float*)d_in[6];
    const float* bv   = (const float*)d_in[7];
    const float* Wo   = (const float*)d_in[8];
    const float* bo   = (const float*)d_in[9];
    float* out = (float*)d_out;

    const int gemm_smem = 4 * TILE_U32 * 4;   // 73728
    cudaFuncSetAttribute(gemm_qkv, cudaFuncAttributeMaxDynamicSharedMemorySize, gemm_smem);
    cudaFuncSetAttribute(gemm_out, cudaFuncAttributeMaxDynamicSharedMemorySize, gemm_smem);
    cudaFuncSetAttribute(attn_mma, cudaFuncAttributeMaxDynamicSharedMemorySize, ATT_SMEM);

    prep_x<<<MTOT * EDIM / 1024, 256>>>(X);

    dim3 tgrid(32, 32, 4), tblk(32, 8);
    transpose4<<<tgrid, tblk>>>(Wq, Wk, Wv, Wo);

    dim3 qkvgrid(MTOT / GBM, EDIM / GBN, 3);   // 32 x 8 x 3
    gemm_qkv<<<qkvgrid, 256, gemm_smem>>>(bq, bk, bv);

    dim3 agrid(SS / 128, BB * NH);             // 16 x 32
    attn_mma<<<agrid, 256, ATT_SMEM>>>(mask);

    dim3 ogrid(MTOT / GBM, EDIM / GBN);        // 32 x 8
    gemm_out<<<ogrid, 256, gemm_smem>>>(bo, out);
}

// round 10
// speedup vs baseline: 1.2642x; 1.0507x over previous
#include <cuda_runtime.h>
#include <math.h>
#include <cstdint>

#define EDIM 1024
#define NH   16
#define HD   64
#define BB   2
#define SS   2048
#define MTOT (BB*SS)   // 4096

// Scratch (tf32 bit patterns stored as uint32)
__device__ uint32_t g_Xt[MTOT*EDIM];
__device__ uint32_t g_Q[MTOT*EDIM];
__device__ uint32_t g_K[MTOT*EDIM];
__device__ uint32_t g_V[MTOT*EDIM];     // TRANSPOSED: [b][h][d][s]
__device__ uint32_t g_ctx[MTOT*EDIM];
__device__ uint32_t g_Wt[4][EDIM*EDIM];

__device__ __forceinline__ uint32_t cvt_tf32(float x) {
    uint32_t r; asm("cvt.rna.tf32.f32 %0, %1;" : "=r"(r) : "f"(x));
    return r;
}
__device__ __forceinline__ void mma_tf32(float& d0, float& d1, float& d2, float& d3,
                                         uint32_t a0, uint32_t a1, uint32_t a2, uint32_t a3,
                                         uint32_t b0, uint32_t b1) {
    asm volatile(
        "mma.sync.aligned.m16n8k8.row.col.f32.tf32.tf32.f32 "
        "{%0,%1,%2,%3},{%4,%5,%6,%7},{%8,%9},{%0,%1,%2,%3};"
        : "+f"(d0), "+f"(d1), "+f"(d2), "+f"(d3)
        : "r"(a0), "r"(a1), "r"(a2), "r"(a3), "r"(b0), "r"(b1));
}
__device__ __forceinline__ void ldsm4(uint32_t& r0, uint32_t& r1, uint32_t& r2, uint32_t& r3,
                                      uint32_t addr) {
    asm volatile("ldmatrix.sync.aligned.m8n8.x4.shared.b16 {%0,%1,%2,%3}, [%4];"
                 : "=r"(r0), "=r"(r1), "=r"(r2), "=r"(r3) : "r"(addr));
}
__device__ __forceinline__ void cp16(uint32_t dst, const void* src) {
    asm volatile("cp.async.cg.shared.global [%0], [%1], 16;" :: "r"(dst), "l"(src));
}
__device__ __forceinline__ void cp_commit() { asm volatile("cp.async.commit_group;"); }
__device__ __forceinline__ void cp_wait0()  { asm volatile("cp.async.wait_group 0;" ::: "memory"); }

// ============================ X -> tf32 prep ============================
__global__ __launch_bounds__(256)
void prep_x(const float* __restrict__ X)
{
    size_t i = ((size_t)blockIdx.x * 256 + threadIdx.x) * 4;
    float4 v = *reinterpret_cast<const float4*>(&X[i]);
    uint4 o;
    o.x = cvt_tf32(v.x); o.y = cvt_tf32(v.y); o.z = cvt_tf32(v.z); o.w = cvt_tf32(v.w);
    *reinterpret_cast<uint4*>(&g_Xt[i]) = o;
}

// ============================ fused transpose (tf32 out) ============================
__global__ __launch_bounds__(256)
void transpose4(const float* __restrict__ w0, const float* __restrict__ w1,
                const float* __restrict__ w2, const float* __restrict__ w3)
{
    const float* in = (blockIdx.z == 0) ? w0 : (blockIdx.z == 1) ? w1 : (blockIdx.z == 2) ? w2 : w3;
    uint32_t* out = g_Wt[blockIdx.z];
    __shared__ float t[32][33];
    int x = blockIdx.x * 32 + threadIdx.x;
    int y = blockIdx.y * 32 + threadIdx.y;
#pragma unroll
    for (int j = 0; j < 32; j += 8)
        t[threadIdx.y + j][threadIdx.x] = in[(size_t)(y + j) * EDIM + x];
    __syncthreads();
    x = blockIdx.y * 32 + threadIdx.x;
    y = blockIdx.x * 32 + threadIdx.y;
#pragma unroll
    for (int j = 0; j < 32; j += 8)
        out[(size_t)(y + j) * EDIM + x] = cvt_tf32(t[threadIdx.x][threadIdx.y + j]);
}

// ============================ tf32 mma.sync GEMM ============================
#define GBM 128
#define GBN 128
#define GBK 32
#define LDP 36
#define TILE_U32 (128 * LDP)

// out_mode: 0 = float row-major; 1 = tf32 [b][h][s][d]; 2 = tf32 [b][h][d][s] (V transposed)
__device__ __forceinline__ void gemm_body(const uint32_t* __restrict__ A,
                                          const uint32_t* __restrict__ Wt,
                                          const float* __restrict__ bias,
                                          void* __restrict__ Cv,
                                          int out_mode, int m0, int n0)
{
    extern __shared__ uint32_t sm[];
    const uint32_t sb = (uint32_t)__cvta_generic_to_shared(sm);

    const int tid = threadIdx.x;
    const int wid = tid >> 5;
    const int lane = tid & 31;
    const int warp_m = (wid & 3) * 32;
    const int warp_n = (wid >> 2) * 64;
    const int r4 = lane >> 2;
    const int c4 = lane & 3;
    const int quad = lane >> 3;
    const int lrow = lane & 7;

    float acc[2][8][4];
#pragma unroll
    for (int mt = 0; mt < 2; mt++)
#pragma unroll
        for (int nt = 0; nt < 8; nt++)
#pragma unroll
            for (int i = 0; i < 4; i++) acc[mt][nt][i] = 0.f;

    const int sr = tid >> 1;
    const int sc = (tid & 1) * 16;
    auto stage = [&](int buf, int k0) {
        uint32_t ad = sb + (uint32_t)((buf * 2 * TILE_U32 + sr * LDP + sc) * 4);
        const uint32_t* Ap = &A[(size_t)(m0 + sr) * EDIM + k0 + sc];
#pragma unroll
        for (int i = 0; i < 4; i++) cp16(ad + i * 16, Ap + i * 4);
        uint32_t bd = sb + (uint32_t)(((buf * 2 + 1) * TILE_U32 + sr * LDP + sc) * 4);
        const uint32_t* Bp = &Wt[(size_t)(n0 + sr) * EDIM + k0 + sc];
#pragma unroll
        for (int i = 0; i < 4; i++) cp16(bd + i * 16, Bp + i * 4);
    };

    const uint32_t aoff = (uint32_t)(((warp_m + (quad & 1) * 8 + lrow) * LDP + (quad >> 1) * 4) * 4);
    const uint32_t boff = (uint32_t)(((warp_n + (quad >> 1) * 8 + lrow) * LDP + (quad & 1) * 4) * 4);

    stage(0, 0);
    cp_commit();

    const int NCHUNK = EDIM / GBK;   // 32
    for (int c = 0; c < NCHUNK; c++) {
        const int cur = c & 1;
        cp_wait0();
        __syncthreads();
        if (c + 1 < NCHUNK) { stage(cur ^ 1, (c + 1) * GBK); cp_commit(); }

        const uint32_t ab = sb + (uint32_t)(cur * 2 * TILE_U32 * 4);
        const uint32_t bb = sb + (uint32_t)((cur * 2 + 1) * TILE_U32 * 4);
#pragma unroll
        for (int ks = 0; ks < 4; ks++) {
            const uint32_t kbb = (uint32_t)(ks * 32);
            uint32_t af[2][4];
#pragma unroll
            for (int mt = 0; mt < 2; mt++)
                ldsm4(af[mt][0], af[mt][1], af[mt][2], af[mt][3],
                      ab + aoff + (uint32_t)(mt * 16 * LDP * 4) + kbb);
            uint32_t bf[8][2];
#pragma unroll
            for (int p = 0; p < 4; p++)
                ldsm4(bf[2 * p][0], bf[2 * p][1], bf[2 * p + 1][0], bf[2 * p + 1][1],
                      bb + boff + (uint32_t)(p * 16 * LDP * 4) + kbb);
#pragma unroll
            for (int mt = 0; mt < 2; mt++)
#pragma unroll
                for (int nt = 0; nt < 8; nt++)
                    mma_tf32(acc[mt][nt][0], acc[mt][nt][1], acc[mt][nt][2], acc[mt][nt][3],
                             af[mt][0], af[mt][1], af[mt][2], af[mt][3],
                             bf[nt][0], bf[nt][1]);
        }
    }

    // ---- epilogue ----
#pragma unroll
    for (int mt = 0; mt < 2; mt++) {
#pragma unroll
        for (int half = 0; half < 2; half++) {
            const int m = m0 + warp_m + mt * 16 + r4 + half * 8;
            const int b_ = m >> 11;
            const int s_ = m & (SS - 1);
#pragma unroll
            for (int nt = 0; nt < 8; nt++) {
                const int col = warp_n + n0 + nt * 8 + 2 * c4;
                float ox = acc[mt][nt][half * 2 + 0] + bias[col];
                float oy = acc[mt][nt][half * 2 + 1] + bias[col + 1];
                if (out_mode == 1) {
                    const int h = col >> 6;
                    const int d = col & (HD - 1);
                    uint32_t* C = (uint32_t*)Cv;
                    *reinterpret_cast<uint2*>(
                        &C[(((size_t)(b_ * NH + h) * SS + s_) * HD) + d]) =
                        make_uint2(cvt_tf32(ox), cvt_tf32(oy));
                } else if (out_mode == 2) {
                    const int h = col >> 6;
                    const int d = col & (HD - 1);
                    uint32_t* C = (uint32_t*)Cv;
                    C[((size_t)(b_ * NH + h) * HD + d) * SS + s_]     = cvt_tf32(ox);
                    C[((size_t)(b_ * NH + h) * HD + d + 1) * SS + s_] = cvt_tf32(oy);
                } else {
                    float* C = (float*)Cv;
                    *reinterpret_cast<float2*>(&C[(size_t)m * EDIM + col]) = make_float2(ox, oy);
                }
            }
        }
    }
}

__global__ __launch_bounds__(256)
void gemm_qkv(const float* __restrict__ bq, const float* __restrict__ bk,
              const float* __restrict__ bv)
{
    const int z = blockIdx.z;
    const float* bias = (z == 0) ? bq : (z == 1) ? bk : bv;
    uint32_t* C = (z == 0) ? g_Q : (z == 1) ? g_K : g_V;
    gemm_body(g_Xt, g_Wt[z], bias, C, (z == 2) ? 2 : 1, blockIdx.x * GBM, blockIdx.y * GBN);
}

__global__ __launch_bounds__(256)
void gemm_out(const float* __restrict__ bo, float* __restrict__ C)
{
    gemm_body(g_ctx, g_Wt[3], bo, C, 0, blockIdx.x * GBM, blockIdx.y * GBN);
}

// ============================ flash attention ============================
#define LKK 68
#define LVT 68
#define LPP 68
#define OFF_K0 0
#define OFF_V0 (64 * LKK)                  // 4352
#define OFF_K1 (OFF_V0 + 64 * LVT)         // 8704
#define OFF_V1 (OFF_K1 + 64 * LKK)
#define OFF_P  (OFF_V1 + 64 * LVT)         // 17408
#define OFF_MD (OFF_P + 8 * 16 * LPP)      // 26112
#define ATT_SMEM ((OFF_MD + 128) * 4)      // 104960 bytes

__global__ __launch_bounds__(256, 2)
void attn_mma(const float* __restrict__ mask)
{
    extern __shared__ uint32_t sm[];
    const uint32_t sb = (uint32_t)__cvta_generic_to_shared(sm);
    float* madds = reinterpret_cast<float*>(sm + OFF_MD);

    const int bh = blockIdx.y;
    const int b_ = bh >> 4;
    const int h  = bh & (NH - 1);
    const int q0 = blockIdx.x * 128;
    const int tid = threadIdx.x;
    const int wid = tid >> 5;
    const int lane = tid & 31;
    const int r4 = lane >> 2;
    const int c4 = lane & 3;
    const int quad = lane >> 3;
    const int lrow = lane & 7;

    const int ks_off[2] = { OFF_K0, OFF_K1 };
    const int vs_off[2] = { OFF_V0, OFF_V1 };
    const int qrow = q0 + wid * 16;

    // Q fragments (raw tf32 bits) in registers for entire KV loop
    uint32_t aq[8][4];
    {
        const uint32_t* Qb = g_Q + ((size_t)bh * SS + qrow) * HD;
#pragma unroll
        for (int ks = 0; ks < 8; ks++) {
            aq[ks][0] = Qb[(size_t)r4 * HD + ks * 8 + c4];
            aq[ks][1] = Qb[(size_t)(r4 + 8) * HD + ks * 8 + c4];
            aq[ks][2] = Qb[(size_t)r4 * HD + ks * 8 + c4 + 4];
            aq[ks][3] = Qb[(size_t)(r4 + 8) * HD + ks * 8 + c4 + 4];
        }
    }

    float ctx[8][4];
#pragma unroll
    for (int nt = 0; nt < 8; nt++)
#pragma unroll
        for (int i = 0; i < 4; i++) ctx[nt][i] = 0.f;
    float m0 = -1e30f, m1 = -1e30f, l0 = 0.f, l1 = 0.f;
    const float scale = 0.125f;

    const int krow = tid >> 2;          // 0..63
    const int kcb = (tid & 3) * 16;     // 0..48

    auto stage = [&](int buf, int kt) {
        // K: [key][d] rows
        const uint32_t* Kp = g_K + ((size_t)bh * SS + kt + krow) * HD + kcb;
        uint32_t kd = sb + (uint32_t)((ks_off[buf] + krow * LKK + kcb) * 4);
#pragma unroll
        for (int i = 0; i < 4; i++) cp16(kd + i * 16, Kp + i * 4);
        // V (transposed in gmem): [d][key] rows
        const uint32_t* Vp = g_V + ((size_t)bh * HD + krow) * SS + kt + kcb;
        uint32_t vd = sb + (uint32_t)((vs_off[buf] + krow * LVT + kcb) * 4);
#pragma unroll
        for (int i = 0; i < 4; i++) cp16(vd + i * 16, Vp + i * 4);
        if (tid < 64)
            madds[buf * 64 + tid] = (1.0f - mask[b_ * SS + kt + tid]) * -10000.0f;
    };

    // ldmatrix lane offsets
    const uint32_t koff = (uint32_t)((((quad >> 1) * 8 + lrow) * LKK + (quad & 1) * 4) * 4);
    const uint32_t voff = (uint32_t)((((quad >> 1) * 8 + lrow) * LVT + (quad & 1) * 4) * 4);
    const uint32_t poff = (uint32_t)((((quad & 1) * 8 + lrow) * LPP + (quad >> 1) * 4) * 4);
    const uint32_t pwbase = sb + (uint32_t)((OFF_P + wid * 16 * LPP) * 4);
    uint32_t* Pw = sm + OFF_P + wid * 16 * LPP;

    stage(0, 0);
    cp_commit();

    const int NT = SS / 64;   // 32
    for (int t = 0; t < NT; t++) {
        const int cur = t & 1;
        cp_wait0();
        __syncthreads();
        if (t + 1 < NT) { stage(cur ^ 1, (t + 1) * 64); cp_commit(); }

        const uint32_t kb = sb + (uint32_t)(ks_off[cur] * 4);
        const uint32_t vb = sb + (uint32_t)(vs_off[cur] * 4);
        const float* madd = &madds[cur * 64];

        // ---- S = Q @ K^T ----
        float sf[8][4];
#pragma unroll
        for (int nt = 0; nt < 8; nt++)
            sf[nt][0] = sf[nt][1] = sf[nt][2] = sf[nt][3] = 0.f;
#pragma unroll
        for (int ks = 0; ks < 8; ks++) {
            uint32_t bf[8][2];
#pragma unroll
            for (int p = 0; p < 4; p++)
                ldsm4(bf[2 * p][0], bf[2 * p][1], bf[2 * p + 1][0], bf[2 * p + 1][1],
                      kb + koff + (uint32_t)(p * 16 * LKK * 4) + (uint32_t)(ks * 32));
#pragma unroll
            for (int nt = 0; nt < 8; nt++)
                mma_tf32(sf[nt][0], sf[nt][1], sf[nt][2], sf[nt][3],
                         aq[ks][0], aq[ks][1], aq[ks][2], aq[ks][3],
                         bf[nt][0], bf[nt][1]);
        }

        // ---- scale + mask + online softmax ----
        float rm0 = -1e30f, rm1 = -1e30f;
#pragma unroll
        for (int nt = 0; nt < 8; nt++) {
            float ma = madd[nt * 8 + 2 * c4];
            float mb = madd[nt * 8 + 2 * c4 + 1];
            sf[nt][0] = sf[nt][0] * scale + ma;
            sf[nt][1] = sf[nt][1] * scale + mb;
            sf[nt][2] = sf[nt][2] * scale + ma;
            sf[nt][3] = sf[nt][3] * scale + mb;
            rm0 = fmaxf(rm0, fmaxf(sf[nt][0], sf[nt][1]));
            rm1 = fmaxf(rm1, fmaxf(sf[nt][2], sf[nt][3]));
        }
        rm0 = fmaxf(rm0, __shfl_xor_sync(0xffffffff, rm0, 1));
        rm0 = fmaxf(rm0, __shfl_xor_sync(0xffffffff, rm0, 2));
        rm1 = fmaxf(rm1, __shfl_xor_sync(0xffffffff, rm1, 1));
        rm1 = fmaxf(rm1, __shfl_xor_sync(0xffffffff, rm1, 2));

        float nm0 = fmaxf(m0, rm0), nm1 = fmaxf(m1, rm1);
        float corr0 = __expf(m0 - nm0), corr1 = __expf(m1 - nm1);
        m0 = nm0; m1 = nm1;

        float rs0 = 0.f, rs1 = 0.f;
#pragma unroll
        for (int nt = 0; nt < 8; nt++) {
            sf[nt][0] = __expf(sf[nt][0] - nm0);
            sf[nt][1] = __expf(sf[nt][1] - nm0);
            sf[nt][2] = __expf(sf[nt][2] - nm1);
            sf[nt][3] = __expf(sf[nt][3] - nm1);
            rs0 += sf[nt][0] + sf[nt][1];
            rs1 += sf[nt][2] + sf[nt][3];
        }
        rs0 += __shfl_xor_sync(0xffffffff, rs0, 1);
        rs0 += __shfl_xor_sync(0xffffffff, rs0, 2);
        rs1 += __shfl_xor_sync(0xffffffff, rs1, 1);
        rs1 += __shfl_xor_sync(0xffffffff, rs1, 2);
        l0 = l0 * corr0 + rs0;
        l1 = l1 * corr1 + rs1;

#pragma unroll
        for (int nt = 0; nt < 8; nt++) {
            ctx[nt][0] *= corr0; ctx[nt][1] *= corr0;
            ctx[nt][2] *= corr1; ctx[nt][3] *= corr1;
        }

        // ---- store P (tf32) to warp-private SMEM ----
#pragma unroll
        for (int nt = 0; nt < 8; nt++) {
            uint2 lo = make_uint2(cvt_tf32(sf[nt][0]), cvt_tf32(sf[nt][1]));
            uint2 hi = make_uint2(cvt_tf32(sf[nt][2]), cvt_tf32(sf[nt][3]));
            *reinterpret_cast<uint2*>(&Pw[r4 * LPP + nt * 8 + 2 * c4]) = lo;
            *reinterpret_cast<uint2*>(&Pw[(r4 + 8) * LPP + nt * 8 + 2 * c4]) = hi;
        }
        __syncwarp();

        // ---- ctx += P @ V  (V fragments via ldmatrix on transposed tile) ----
#pragma unroll
        for (int ks2 = 0; ks2 < 8; ks2++) {
            uint32_t ap0, ap1, ap2, ap3;
            ldsm4(ap0, ap1, ap2, ap3, pwbase + poff + (uint32_t)(ks2 * 32));
            uint32_t vf[8][2];
#pragma unroll
            for (int p = 0; p < 4; p++)
                ldsm4(vf[2 * p][0], vf[2 * p][1], vf[2 * p + 1][0], vf[2 * p + 1][1],
                      vb + voff + (uint32_t)(p * 16 * LVT * 4) + (uint32_t)(ks2 * 32));
#pragma unroll
            for (int nt2 = 0; nt2 < 8; nt2++)
                mma_tf32(ctx[nt2][0], ctx[nt2][1], ctx[nt2][2], ctx[nt2][3],
                         ap0, ap1, ap2, ap3, vf[nt2][0], vf[nt2][1]);
        }
        __syncwarp();
    }

    // ---- epilogue: normalize, write tf32 bits to g_ctx [B,S,E] ----
    float inv0 = 1.0f / l0;
    float inv1 = 1.0f / l1;
    const int sq0 = qrow + r4;
    uint32_t* C0 = g_ctx + ((size_t)(b_ * SS + sq0) * EDIM) + h * HD;
    uint32_t* C1 = g_ctx + ((size_t)(b_ * SS + sq0 + 8) * EDIM) + h * HD;
#pragma unroll
    for (int nt2 = 0; nt2 < 8; nt2++) {
        const int col = nt2 * 8 + 2 * c4;
        *reinterpret_cast<uint2*>(&C0[col]) =
            make_uint2(cvt_tf32(ctx[nt2][0] * inv0), cvt_tf32(ctx[nt2][1] * inv0));
        *reinterpret_cast<uint2*>(&C1[col]) =
            make_uint2(cvt_tf32(ctx[nt2][2] * inv1), cvt_tf32(ctx[nt2][3] * inv1));
    }
}

// ============================ launch ============================
extern "C" void kernel_launch(void* const* d_in, const int* in_sizes, int n_in,
                              void* d_out, int out_size)
{
    const float* X    = (const float*)d_in[0];
    const float* mask = (const float*)d_in[1];
    const float* Wq   = (const float*)d_in[2];
    const float* bq   = (const float*)d_in[3];
    const float* Wk   = (const float*)d_in[4];
    const float* bk   = (const float*)d_in[5];
    const float* Wv   = (const float*)d_in[6];
    const float* bv   = (const float*)d_in[7];
    const float* Wo   = (const float*)d_in[8];
    const float* bo   = (const float*)d_in[9];
    float* out = (float*)d_out;

    const int gemm_smem = 4 * TILE_U32 * 4;   // 73728
    cudaFuncSetAttribute(gemm_qkv, cudaFuncAttributeMaxDynamicSharedMemorySize, gemm_smem);
    cudaFuncSetAttribute(gemm_out, cudaFuncAttributeMaxDynamicSharedMemorySize, gemm_smem);
    cudaFuncSetAttribute(attn_mma, cudaFuncAttributeMaxDynamicSharedMemorySize, ATT_SMEM);

    prep_x<<<MTOT * EDIM / 1024, 256>>>(X);

    dim3 tgrid(32, 32, 4), tblk(32, 8);
    transpose4<<<tgrid, tblk>>>(Wq, Wk, Wv, Wo);

    dim3 qkvgrid(MTOT / GBM, EDIM / GBN, 3);   // 32 x 8 x 3
    gemm_qkv<<<qkvgrid, 256, gemm_smem>>>(bq, bk, bv);

    dim3 agrid(SS / 128, BB * NH);             // 16 x 32
    attn_mma<<<agrid, 256, ATT_SMEM>>>(mask);

    dim3 ogrid(MTOT / GBM, EDIM / GBN);        // 32 x 8
    gemm_out<<<ogrid, 256, gemm_smem>>>(bo, out);
}

// round 11
// speedup vs baseline: 1.3130x; 1.0386x over previous
#include <cuda_runtime.h>
#include <math.h>
#include <cstdint>

#define EDIM 1024
#define NH   16
#define HD   64
#define BB   2
#define SS   2048
#define MTOT (BB*SS)   // 4096

// Scratch (tf32 bit patterns stored as uint32)
__device__ uint32_t g_Xt[MTOT*EDIM];
__device__ uint32_t g_Q[MTOT*EDIM];
__device__ uint32_t g_K[MTOT*EDIM];
__device__ uint32_t g_V[MTOT*EDIM];     // TRANSPOSED: [b][h][d][s]
__device__ uint32_t g_ctx[MTOT*EDIM];
__device__ uint32_t g_Wt[4][EDIM*EDIM];

__device__ __forceinline__ uint32_t cvt_tf32(float x) {
    uint32_t r; asm("cvt.rna.tf32.f32 %0, %1;" : "=r"(r) : "f"(x));
    return r;
}
__device__ __forceinline__ void mma_tf32(float& d0, float& d1, float& d2, float& d3,
                                         uint32_t a0, uint32_t a1, uint32_t a2, uint32_t a3,
                                         uint32_t b0, uint32_t b1) {
    asm volatile(
        "mma.sync.aligned.m16n8k8.row.col.f32.tf32.tf32.f32 "
        "{%0,%1,%2,%3},{%4,%5,%6,%7},{%8,%9},{%0,%1,%2,%3};"
        : "+f"(d0), "+f"(d1), "+f"(d2), "+f"(d3)
        : "r"(a0), "r"(a1), "r"(a2), "r"(a3), "r"(b0), "r"(b1));
}
__device__ __forceinline__ void ldsm4(uint32_t& r0, uint32_t& r1, uint32_t& r2, uint32_t& r3,
                                      uint32_t addr) {
    asm volatile("ldmatrix.sync.aligned.m8n8.x4.shared.b16 {%0,%1,%2,%3}, [%4];"
                 : "=r"(r0), "=r"(r1), "=r"(r2), "=r"(r3) : "r"(addr));
}
__device__ __forceinline__ void cp16(uint32_t dst, const void* src) {
    asm volatile("cp.async.cg.shared.global [%0], [%1], 16;" :: "r"(dst), "l"(src));
}
__device__ __forceinline__ void cp_commit() { asm volatile("cp.async.commit_group;"); }
__device__ __forceinline__ void cp_wait0()  { asm volatile("cp.async.wait_group 0;" ::: "memory"); }

// ============================ X -> tf32 prep ============================
__global__ __launch_bounds__(256)
void prep_x(const float* __restrict__ X)
{
    size_t i = ((size_t)blockIdx.x * 256 + threadIdx.x) * 4;
    float4 v = *reinterpret_cast<const float4*>(&X[i]);
    uint4 o;
    o.x = cvt_tf32(v.x); o.y = cvt_tf32(v.y); o.z = cvt_tf32(v.z); o.w = cvt_tf32(v.w);
    *reinterpret_cast<uint4*>(&g_Xt[i]) = o;
}

// ============================ fused transpose (tf32 out) ============================
__global__ __launch_bounds__(256)
void transpose4(const float* __restrict__ w0, const float* __restrict__ w1,
                const float* __restrict__ w2, const float* __restrict__ w3)
{
    const float* in = (blockIdx.z == 0) ? w0 : (blockIdx.z == 1) ? w1 : (blockIdx.z == 2) ? w2 : w3;
    uint32_t* out = g_Wt[blockIdx.z];
    __shared__ float t[32][33];
    int x = blockIdx.x * 32 + threadIdx.x;
    int y = blockIdx.y * 32 + threadIdx.y;
#pragma unroll
    for (int j = 0; j < 32; j += 8)
        t[threadIdx.y + j][threadIdx.x] = in[(size_t)(y + j) * EDIM + x];
    __syncthreads();
    x = blockIdx.y * 32 + threadIdx.x;
    y = blockIdx.x * 32 + threadIdx.y;
#pragma unroll
    for (int j = 0; j < 32; j += 8)
        out[(size_t)(y + j) * EDIM + x] = cvt_tf32(t[threadIdx.x][threadIdx.y + j]);
}

// ============================ tf32 mma.sync GEMM ============================
#define GBM 128
#define GBN 128
#define GBK 32
#define LDP 36
#define TILE_U32 (128 * LDP)

// out_mode: 0 = float row-major; 1 = tf32 [b][h][s][d]; 2 = tf32 [b][h][d][s] (V transposed)
__device__ __forceinline__ void gemm_body(const uint32_t* __restrict__ A,
                                          const uint32_t* __restrict__ Wt,
                                          const float* __restrict__ bias,
                                          void* __restrict__ Cv,
                                          int out_mode, int m0, int n0)
{
    extern __shared__ uint32_t sm[];
    const uint32_t sb = (uint32_t)__cvta_generic_to_shared(sm);

    const int tid = threadIdx.x;
    const int wid = tid >> 5;
    const int lane = tid & 31;
    const int warp_m = (wid & 3) * 32;
    const int warp_n = (wid >> 2) * 64;
    const int r4 = lane >> 2;
    const int c4 = lane & 3;
    const int quad = lane >> 3;
    const int lrow = lane & 7;

    float acc[2][8][4];
#pragma unroll
    for (int mt = 0; mt < 2; mt++)
#pragma unroll
        for (int nt = 0; nt < 8; nt++)
#pragma unroll
            for (int i = 0; i < 4; i++) acc[mt][nt][i] = 0.f;

    const int sr = tid >> 1;
    const int sc = (tid & 1) * 16;
    auto stage = [&](int buf, int k0) {
        uint32_t ad = sb + (uint32_t)((buf * 2 * TILE_U32 + sr * LDP + sc) * 4);
        const uint32_t* Ap = &A[(size_t)(m0 + sr) * EDIM + k0 + sc];
#pragma unroll
        for (int i = 0; i < 4; i++) cp16(ad + i * 16, Ap + i * 4);
        uint32_t bd = sb + (uint32_t)(((buf * 2 + 1) * TILE_U32 + sr * LDP + sc) * 4);
        const uint32_t* Bp = &Wt[(size_t)(n0 + sr) * EDIM + k0 + sc];
#pragma unroll
        for (int i = 0; i < 4; i++) cp16(bd + i * 16, Bp + i * 4);
    };

    const uint32_t aoff = (uint32_t)(((warp_m + (quad & 1) * 8 + lrow) * LDP + (quad >> 1) * 4) * 4);
    const uint32_t boff = (uint32_t)(((warp_n + (quad >> 1) * 8 + lrow) * LDP + (quad & 1) * 4) * 4);

    stage(0, 0);
    cp_commit();

    const int NCHUNK = EDIM / GBK;   // 32
    for (int c = 0; c < NCHUNK; c++) {
        const int cur = c & 1;
        cp_wait0();
        __syncthreads();
        if (c + 1 < NCHUNK) { stage(cur ^ 1, (c + 1) * GBK); cp_commit(); }

        const uint32_t ab = sb + (uint32_t)(cur * 2 * TILE_U32 * 4);
        const uint32_t bb = sb + (uint32_t)((cur * 2 + 1) * TILE_U32 * 4);
#pragma unroll
        for (int ks = 0; ks < 4; ks++) {
            const uint32_t kbb = (uint32_t)(ks * 32);
            uint32_t af[2][4];
#pragma unroll
            for (int mt = 0; mt < 2; mt++)
                ldsm4(af[mt][0], af[mt][1], af[mt][2], af[mt][3],
                      ab + aoff + (uint32_t)(mt * 16 * LDP * 4) + kbb);
            uint32_t bf[8][2];
#pragma unroll
            for (int p = 0; p < 4; p++)
                ldsm4(bf[2 * p][0], bf[2 * p][1], bf[2 * p + 1][0], bf[2 * p + 1][1],
                      bb + boff + (uint32_t)(p * 16 * LDP * 4) + kbb);
#pragma unroll
            for (int mt = 0; mt < 2; mt++)
#pragma unroll
                for (int nt = 0; nt < 8; nt++)
                    mma_tf32(acc[mt][nt][0], acc[mt][nt][1], acc[mt][nt][2], acc[mt][nt][3],
                             af[mt][0], af[mt][1], af[mt][2], af[mt][3],
                             bf[nt][0], bf[nt][1]);
        }
    }

    // ---- epilogue ----
#pragma unroll
    for (int mt = 0; mt < 2; mt++) {
#pragma unroll
        for (int half = 0; half < 2; half++) {
            const int m = m0 + warp_m + mt * 16 + r4 + half * 8;
            const int b_ = m >> 11;
            const int s_ = m & (SS - 1);
#pragma unroll
            for (int nt = 0; nt < 8; nt++) {
                const int col = warp_n + n0 + nt * 8 + 2 * c4;
                float ox = acc[mt][nt][half * 2 + 0] + bias[col];
                float oy = acc[mt][nt][half * 2 + 1] + bias[col + 1];
                if (out_mode == 1) {
                    const int h = col >> 6;
                    const int d = col & (HD - 1);
                    uint32_t* C = (uint32_t*)Cv;
                    *reinterpret_cast<uint2*>(
                        &C[(((size_t)(b_ * NH + h) * SS + s_) * HD) + d]) =
                        make_uint2(cvt_tf32(ox), cvt_tf32(oy));
                } else if (out_mode == 2) {
                    const int h = col >> 6;
                    const int d = col & (HD - 1);
                    uint32_t* C = (uint32_t*)Cv;
                    C[((size_t)(b_ * NH + h) * HD + d) * SS + s_]     = cvt_tf32(ox);
                    C[((size_t)(b_ * NH + h) * HD + d + 1) * SS + s_] = cvt_tf32(oy);
                } else {
                    float* C = (float*)Cv;
                    *reinterpret_cast<float2*>(&C[(size_t)m * EDIM + col]) = make_float2(ox, oy);
                }
            }
        }
    }
}

__global__ __launch_bounds__(256)
void gemm_qkv(const float* __restrict__ bq, const float* __restrict__ bk,
              const float* __restrict__ bv)
{
    const int z = blockIdx.z;
    const float* bias = (z == 0) ? bq : (z == 1) ? bk : bv;
    uint32_t* C = (z == 0) ? g_Q : (z == 1) ? g_K : g_V;
    gemm_body(g_Xt, g_Wt[z], bias, C, (z == 2) ? 2 : 1, blockIdx.x * GBM, blockIdx.y * GBN);
}

__global__ __launch_bounds__(256)
void gemm_out(const float* __restrict__ bo, float* __restrict__ C)
{
    gemm_body(g_ctx, g_Wt[3], bo, C, 0, blockIdx.x * GBM, blockIdx.y * GBN);
}

// ============================ flash attention: 32 q rows per warp ============================
#define LKK 68
#define LVT 68
#define LPP 68
#define OFF_K0 0
#define OFF_V0 (64 * LKK)                  // 4352
#define OFF_K1 (OFF_V0 + 64 * LVT)         // 8704
#define OFF_V1 (OFF_K1 + 64 * LKK)         // 13056
#define OFF_P  (OFF_V1 + 64 * LVT)         // 17408
#define OFF_MD (OFF_P + 8 * 32 * LPP)      // 34816
#define ATT_SMEM ((OFF_MD + 128) * 4)      // 139776 bytes

__global__ __launch_bounds__(256, 1)
void attn_mma(const float* __restrict__ mask)
{
    extern __shared__ uint32_t sm[];
    const uint32_t sb = (uint32_t)__cvta_generic_to_shared(sm);
    float* madds = reinterpret_cast<float*>(sm + OFF_MD);

    const int bh = blockIdx.y;
    const int b_ = bh >> 4;
    const int h  = bh & (NH - 1);
    const int q0 = blockIdx.x * 256;
    const int tid = threadIdx.x;
    const int wid = tid >> 5;
    const int lane = tid & 31;
    const int r4 = lane >> 2;
    const int c4 = lane & 3;
    const int quad = lane >> 3;
    const int lrow = lane & 7;

    const int ks_off[2] = { OFF_K0, OFF_K1 };
    const int vs_off[2] = { OFF_V0, OFF_V1 };
    const int qrow = q0 + wid * 32;

    // Q fragments for 32 rows (2 m16 tiles) in registers for entire KV loop
    uint32_t aq[2][8][4];
    {
        const uint32_t* Qb = g_Q + ((size_t)bh * SS + qrow) * HD;
#pragma unroll
        for (int mt = 0; mt < 2; mt++)
#pragma unroll
            for (int ks = 0; ks < 8; ks++) {
                const uint32_t* R0 = &Qb[(size_t)(mt * 16 + r4) * HD + ks * 8 + c4];
                const uint32_t* R1 = &Qb[(size_t)(mt * 16 + r4 + 8) * HD + ks * 8 + c4];
                aq[mt][ks][0] = R0[0];
                aq[mt][ks][1] = R1[0];
                aq[mt][ks][2] = R0[4];
                aq[mt][ks][3] = R1[4];
            }
    }

    float ctx[2][8][4];
#pragma unroll
    for (int mt = 0; mt < 2; mt++)
#pragma unroll
        for (int nt = 0; nt < 8; nt++)
#pragma unroll
            for (int i = 0; i < 4; i++) ctx[mt][nt][i] = 0.f;
    float mx[2][2], lsum[2][2];
#pragma unroll
    for (int mt = 0; mt < 2; mt++) {
        mx[mt][0] = mx[mt][1] = -1e30f;
        lsum[mt][0] = lsum[mt][1] = 0.f;
    }
    const float scale = 0.125f;

    const int krow = tid >> 2;          // 0..63
    const int kcb = (tid & 3) * 16;     // 0..48

    auto stage = [&](int buf, int kt) {
        const uint32_t* Kp = g_K + ((size_t)bh * SS + kt + krow) * HD + kcb;
        uint32_t kd = sb + (uint32_t)((ks_off[buf] + krow * LKK + kcb) * 4);
#pragma unroll
        for (int i = 0; i < 4; i++) cp16(kd + i * 16, Kp + i * 4);
        const uint32_t* Vp = g_V + ((size_t)bh * HD + krow) * SS + kt + kcb;
        uint32_t vd = sb + (uint32_t)((vs_off[buf] + krow * LVT + kcb) * 4);
#pragma unroll
        for (int i = 0; i < 4; i++) cp16(vd + i * 16, Vp + i * 4);
        if (tid < 64)
            madds[buf * 64 + tid] = (1.0f - mask[b_ * SS + kt + tid]) * -10000.0f;
    };

    const uint32_t koff = (uint32_t)((((quad >> 1) * 8 + lrow) * LKK + (quad & 1) * 4) * 4);
    const uint32_t voff = (uint32_t)((((quad >> 1) * 8 + lrow) * LVT + (quad & 1) * 4) * 4);
    const uint32_t poff = (uint32_t)((((quad & 1) * 8 + lrow) * LPP + (quad >> 1) * 4) * 4);
    const uint32_t pwbase = sb + (uint32_t)((OFF_P + wid * 32 * LPP) * 4);
    uint32_t* Pw = sm + OFF_P + wid * 32 * LPP;

    stage(0, 0);
    cp_commit();

    const int NT = SS / 64;   // 32
    for (int t = 0; t < NT; t++) {
        const int cur = t & 1;
        cp_wait0();
        __syncthreads();
        if (t + 1 < NT) { stage(cur ^ 1, (t + 1) * 64); cp_commit(); }

        const uint32_t kb = sb + (uint32_t)(ks_off[cur] * 4);
        const uint32_t vb = sb + (uint32_t)(vs_off[cur] * 4);
        const float* madd = &madds[cur * 64];

        // ---- S = Q @ K^T (K fragments shared across both m-tiles) ----
        float sf[2][8][4];
#pragma unroll
        for (int mt = 0; mt < 2; mt++)
#pragma unroll
            for (int nt = 0; nt < 8; nt++)
                sf[mt][nt][0] = sf[mt][nt][1] = sf[mt][nt][2] = sf[mt][nt][3] = 0.f;
#pragma unroll
        for (int ks = 0; ks < 8; ks++) {
            uint32_t bf[8][2];
#pragma unroll
            for (int p = 0; p < 4; p++)
                ldsm4(bf[2 * p][0], bf[2 * p][1], bf[2 * p + 1][0], bf[2 * p + 1][1],
                      kb + koff + (uint32_t)(p * 16 * LKK * 4) + (uint32_t)(ks * 32));
#pragma unroll
            for (int mt = 0; mt < 2; mt++)
#pragma unroll
                for (int nt = 0; nt < 8; nt++)
                    mma_tf32(sf[mt][nt][0], sf[mt][nt][1], sf[mt][nt][2], sf[mt][nt][3],
                             aq[mt][ks][0], aq[mt][ks][1], aq[mt][ks][2], aq[mt][ks][3],
                             bf[nt][0], bf[nt][1]);
        }

        // ---- scale + mask + online softmax + P store, per m-tile ----
#pragma unroll
        for (int mt = 0; mt < 2; mt++) {
            float rm0 = -1e30f, rm1 = -1e30f;
#pragma unroll
            for (int nt = 0; nt < 8; nt++) {
                float ma = madd[nt * 8 + 2 * c4];
                float mb = madd[nt * 8 + 2 * c4 + 1];
                sf[mt][nt][0] = sf[mt][nt][0] * scale + ma;
                sf[mt][nt][1] = sf[mt][nt][1] * scale + mb;
                sf[mt][nt][2] = sf[mt][nt][2] * scale + ma;
                sf[mt][nt][3] = sf[mt][nt][3] * scale + mb;
                rm0 = fmaxf(rm0, fmaxf(sf[mt][nt][0], sf[mt][nt][1]));
                rm1 = fmaxf(rm1, fmaxf(sf[mt][nt][2], sf[mt][nt][3]));
            }
            rm0 = fmaxf(rm0, __shfl_xor_sync(0xffffffff, rm0, 1));
            rm0 = fmaxf(rm0, __shfl_xor_sync(0xffffffff, rm0, 2));
            rm1 = fmaxf(rm1, __shfl_xor_sync(0xffffffff, rm1, 1));
            rm1 = fmaxf(rm1, __shfl_xor_sync(0xffffffff, rm1, 2));

            float nm0 = fmaxf(mx[mt][0], rm0), nm1 = fmaxf(mx[mt][1], rm1);
            float corr0 = __expf(mx[mt][0] - nm0), corr1 = __expf(mx[mt][1] - nm1);
            mx[mt][0] = nm0; mx[mt][1] = nm1;

            float rs0 = 0.f, rs1 = 0.f;
#pragma unroll
            for (int nt = 0; nt < 8; nt++) {
                sf[mt][nt][0] = __expf(sf[mt][nt][0] - nm0);
                sf[mt][nt][1] = __expf(sf[mt][nt][1] - nm0);
                sf[mt][nt][2] = __expf(sf[mt][nt][2] - nm1);
                sf[mt][nt][3] = __expf(sf[mt][nt][3] - nm1);
                rs0 += sf[mt][nt][0] + sf[mt][nt][1];
                rs1 += sf[mt][nt][2] + sf[mt][nt][3];
            }
            rs0 += __shfl_xor_sync(0xffffffff, rs0, 1);
            rs0 += __shfl_xor_sync(0xffffffff, rs0, 2);
            rs1 += __shfl_xor_sync(0xffffffff, rs1, 1);
            rs1 += __shfl_xor_sync(0xffffffff, rs1, 2);
            lsum[mt][0] = lsum[mt][0] * corr0 + rs0;
            lsum[mt][1] = lsum[mt][1] * corr1 + rs1;

#pragma unroll
            for (int nt = 0; nt < 8; nt++) {
                ctx[mt][nt][0] *= corr0; ctx[mt][nt][1] *= corr0;
                ctx[mt][nt][2] *= corr1; ctx[mt][nt][3] *= corr1;
            }

            uint32_t* Pm = Pw + mt * 16 * LPP;
#pragma unroll
            for (int nt = 0; nt < 8; nt++) {
                uint2 lo = make_uint2(cvt_tf32(sf[mt][nt][0]), cvt_tf32(sf[mt][nt][1]));
                uint2 hi = make_uint2(cvt_tf32(sf[mt][nt][2]), cvt_tf32(sf[mt][nt][3]));
                *reinterpret_cast<uint2*>(&Pm[r4 * LPP + nt * 8 + 2 * c4]) = lo;
                *reinterpret_cast<uint2*>(&Pm[(r4 + 8) * LPP + nt * 8 + 2 * c4]) = hi;
            }
        }
        __syncwarp();

        // ---- ctx += P @ V (V fragments shared across both m-tiles) ----
#pragma unroll
        for (int ks2 = 0; ks2 < 8; ks2++) {
            uint32_t ap[2][4];
#pragma unroll
            for (int mt = 0; mt < 2; mt++)
                ldsm4(ap[mt][0], ap[mt][1], ap[mt][2], ap[mt][3],
                      pwbase + poff + (uint32_t)(mt * 16 * LPP * 4) + (uint32_t)(ks2 * 32));
            uint32_t vf[8][2];
#pragma unroll
            for (int p = 0; p < 4; p++)
                ldsm4(vf[2 * p][0], vf[2 * p][1], vf[2 * p + 1][0], vf[2 * p + 1][1],
                      vb + voff + (uint32_t)(p * 16 * LVT * 4) + (uint32_t)(ks2 * 32));
#pragma unroll
            for (int mt = 0; mt < 2; mt++)
#pragma unroll
                for (int nt2 = 0; nt2 < 8; nt2++)
                    mma_tf32(ctx[mt][nt2][0], ctx[mt][nt2][1], ctx[mt][nt2][2], ctx[mt][nt2][3],
                             ap[mt][0], ap[mt][1], ap[mt][2], ap[mt][3],
                             vf[nt2][0], vf[nt2][1]);
        }
        __syncwarp();
    }

    // ---- epilogue: normalize, write tf32 bits to g_ctx [B,S,E] ----
#pragma unroll
    for (int mt = 0; mt < 2; mt++) {
        float inv0 = 1.0f / lsum[mt][0];
        float inv1 = 1.0f / lsum[mt][1];
        const int sq0 = qrow + mt * 16 + r4;
        uint32_t* C0 = g_ctx + ((size_t)(b_ * SS + sq0) * EDIM) + h * HD;
        uint32_t* C1 = g_ctx + ((size_t)(b_ * SS + sq0 + 8) * EDIM) + h * HD;
#pragma unroll
        for (int nt2 = 0; nt2 < 8; nt2++) {
            const int col = nt2 * 8 + 2 * c4;
            *reinterpret_cast<uint2*>(&C0[col]) =
                make_uint2(cvt_tf32(ctx[mt][nt2][0] * inv0), cvt_tf32(ctx[mt][nt2][1] * inv0));
            *reinterpret_cast<uint2*>(&C1[col]) =
                make_uint2(cvt_tf32(ctx[mt][nt2][2] * inv1), cvt_tf32(ctx[mt][nt2][3] * inv1));
        }
    }
}

// ============================ launch ============================
extern "C" void kernel_launch(void* const* d_in, const int* in_sizes, int n_in,
                              void* d_out, int out_size)
{
    const float* X    = (const float*)d_in[0];
    const float* mask = (const float*)d_in[1];
    const float* Wq   = (const float*)d_in[2];
    const float* bq   = (const float*)d_in[3];
    const float* Wk   = (const float*)d_in[4];
    const float* bk   = (const float*)d_in[5];
    const float* Wv   = (const float*)d_in[6];
    const float* bv   = (const float*)d_in[7];
    const float* Wo   = (const float*)d_in[8];
    const float* bo   = (const float*)d_in[9];
    float* out = (float*)d_out;

    const int gemm_smem = 4 * TILE_U32 * 4;   // 73728
    cudaFuncSetAttribute(gemm_qkv, cudaFuncAttributeMaxDynamicSharedMemorySize, gemm_smem);
    cudaFuncSetAttribute(gemm_out, cudaFuncAttributeMaxDynamicSharedMemorySize, gemm_smem);
    cudaFuncSetAttribute(attn_mma, cudaFuncAttributeMaxDynamicSharedMemorySize, ATT_SMEM);

    prep_x<<<MTOT * EDIM / 1024, 256>>>(X);

    dim3 tgrid(32, 32, 4), tblk(32, 8);
    transpose4<<<tgrid, tblk>>>(Wq, Wk, Wv, Wo);

    dim3 qkvgrid(MTOT / GBM, EDIM / GBN, 3);   // 32 x 8 x 3
    gemm_qkv<<<qkvgrid, 256, gemm_smem>>>(bq, bk, bv);

    dim3 agrid(SS / 256, BB * NH);             // 8 x 32
    attn_mma<<<agrid, 256, ATT_SMEM>>>(mask);

    dim3 ogrid(MTOT / GBM, EDIM / GBN);        // 32 x 8
    gemm_out<<<ogrid, 256, gemm_smem>>>(bo, out);
}

// round 12
// speedup vs baseline: 1.3353x; 1.0170x over previous
#include <cuda_runtime.h>
#include <math.h>
#include <cstdint>

#define EDIM 1024
#define NH   16
#define HD   64
#define BB   2
#define SS   2048
#define MTOT (BB*SS)   // 4096

// Scratch (tf32 bit patterns stored as uint32)
__device__ uint32_t g_Xt[MTOT*EDIM];
__device__ uint32_t g_Q[MTOT*EDIM];
__device__ uint32_t g_K[MTOT*EDIM];
__device__ uint32_t g_V[MTOT*EDIM];     // TRANSPOSED: [b][h][d][s]
__device__ uint32_t g_ctx[MTOT*EDIM];
__device__ uint32_t g_Wt[4][EDIM*EDIM];

__device__ __forceinline__ uint32_t cvt_tf32(float x) {
    uint32_t r; asm("cvt.rna.tf32.f32 %0, %1;" : "=r"(r) : "f"(x));
    return r;
}
__device__ __forceinline__ void mma_tf32(float& d0, float& d1, float& d2, float& d3,
                                         uint32_t a0, uint32_t a1, uint32_t a2, uint32_t a3,
                                         uint32_t b0, uint32_t b1) {
    asm volatile(
        "mma.sync.aligned.m16n8k8.row.col.f32.tf32.tf32.f32 "
        "{%0,%1,%2,%3},{%4,%5,%6,%7},{%8,%9},{%0,%1,%2,%3};"
        : "+f"(d0), "+f"(d1), "+f"(d2), "+f"(d3)
        : "r"(a0), "r"(a1), "r"(a2), "r"(a3), "r"(b0), "r"(b1));
}
__device__ __forceinline__ void ldsm4(uint32_t& r0, uint32_t& r1, uint32_t& r2, uint32_t& r3,
                                      uint32_t addr) {
    asm volatile("ldmatrix.sync.aligned.m8n8.x4.shared.b16 {%0,%1,%2,%3}, [%4];"
                 : "=r"(r0), "=r"(r1), "=r"(r2), "=r"(r3) : "r"(addr));
}
__device__ __forceinline__ void cp16(uint32_t dst, const void* src) {
    asm volatile("cp.async.cg.shared.global [%0], [%1], 16;" :: "r"(dst), "l"(src));
}
__device__ __forceinline__ void cp_commit() { asm volatile("cp.async.commit_group;"); }
__device__ __forceinline__ void cp_wait0()  { asm volatile("cp.async.wait_group 0;" ::: "memory"); }

// ============================ X -> tf32 prep ============================
__global__ __launch_bounds__(256)
void prep_x(const float* __restrict__ X)
{
    size_t i = ((size_t)blockIdx.x * 256 + threadIdx.x) * 4;
    float4 v = *reinterpret_cast<const float4*>(&X[i]);
    uint4 o;
    o.x = cvt_tf32(v.x); o.y = cvt_tf32(v.y); o.z = cvt_tf32(v.z); o.w = cvt_tf32(v.w);
    *reinterpret_cast<uint4*>(&g_Xt[i]) = o;
}

// ============================ fused transpose (tf32 out) ============================
__global__ __launch_bounds__(256)
void transpose4(const float* __restrict__ w0, const float* __restrict__ w1,
                const float* __restrict__ w2, const float* __restrict__ w3)
{
    const float* in = (blockIdx.z == 0) ? w0 : (blockIdx.z == 1) ? w1 : (blockIdx.z == 2) ? w2 : w3;
    uint32_t* out = g_Wt[blockIdx.z];
    __shared__ float t[32][33];
    int x = blockIdx.x * 32 + threadIdx.x;
    int y = blockIdx.y * 32 + threadIdx.y;
#pragma unroll
    for (int j = 0; j < 32; j += 8)
        t[threadIdx.y + j][threadIdx.x] = in[(size_t)(y + j) * EDIM + x];
    __syncthreads();
    x = blockIdx.y * 32 + threadIdx.x;
    y = blockIdx.x * 32 + threadIdx.y;
#pragma unroll
    for (int j = 0; j < 32; j += 8)
        out[(size_t)(y + j) * EDIM + x] = cvt_tf32(t[threadIdx.x][threadIdx.y + j]);
}

// ============================ tf32 mma.sync GEMM ============================
#define GBM 128
#define GBN 128
#define GBK 32
#define LDP 36
#define TILE_U32 (128 * LDP)

// out_mode: 0 = float row-major; 1 = tf32 [b][h][s][d]; 2 = tf32 [b][h][d][s] (V transposed)
__device__ __forceinline__ void gemm_body(const uint32_t* __restrict__ A,
                                          const uint32_t* __restrict__ Wt,
                                          const float* __restrict__ bias,
                                          void* __restrict__ Cv,
                                          int out_mode, int m0, int n0)
{
    extern __shared__ uint32_t sm[];
    const uint32_t sb = (uint32_t)__cvta_generic_to_shared(sm);

    const int tid = threadIdx.x;
    const int wid = tid >> 5;
    const int lane = tid & 31;
    const int warp_m = (wid & 3) * 32;
    const int warp_n = (wid >> 2) * 64;
    const int r4 = lane >> 2;
    const int c4 = lane & 3;
    const int quad = lane >> 3;
    const int lrow = lane & 7;

    float acc[2][8][4];
#pragma unroll
    for (int mt = 0; mt < 2; mt++)
#pragma unroll
        for (int nt = 0; nt < 8; nt++)
#pragma unroll
            for (int i = 0; i < 4; i++) acc[mt][nt][i] = 0.f;

    const int sr = tid >> 1;
    const int sc = (tid & 1) * 16;
    auto stage = [&](int buf, int k0) {
        uint32_t ad = sb + (uint32_t)((buf * 2 * TILE_U32 + sr * LDP + sc) * 4);
        const uint32_t* Ap = &A[(size_t)(m0 + sr) * EDIM + k0 + sc];
#pragma unroll
        for (int i = 0; i < 4; i++) cp16(ad + i * 16, Ap + i * 4);
        uint32_t bd = sb + (uint32_t)(((buf * 2 + 1) * TILE_U32 + sr * LDP + sc) * 4);
        const uint32_t* Bp = &Wt[(size_t)(n0 + sr) * EDIM + k0 + sc];
#pragma unroll
        for (int i = 0; i < 4; i++) cp16(bd + i * 16, Bp + i * 4);
    };

    const uint32_t aoff = (uint32_t)(((warp_m + (quad & 1) * 8 + lrow) * LDP + (quad >> 1) * 4) * 4);
    const uint32_t boff = (uint32_t)(((warp_n + (quad >> 1) * 8 + lrow) * LDP + (quad & 1) * 4) * 4);

    stage(0, 0);
    cp_commit();

    const int NCHUNK = EDIM / GBK;   // 32
    for (int c = 0; c < NCHUNK; c++) {
        const int cur = c & 1;
        cp_wait0();
        __syncthreads();
        if (c + 1 < NCHUNK) { stage(cur ^ 1, (c + 1) * GBK); cp_commit(); }

        const uint32_t ab = sb + (uint32_t)(cur * 2 * TILE_U32 * 4);
        const uint32_t bb = sb + (uint32_t)((cur * 2 + 1) * TILE_U32 * 4);
#pragma unroll
        for (int ks = 0; ks < 4; ks++) {
            const uint32_t kbb = (uint32_t)(ks * 32);
            uint32_t af[2][4];
#pragma unroll
            for (int mt = 0; mt < 2; mt++)
                ldsm4(af[mt][0], af[mt][1], af[mt][2], af[mt][3],
                      ab + aoff + (uint32_t)(mt * 16 * LDP * 4) + kbb);
            uint32_t bf[8][2];
#pragma unroll
            for (int p = 0; p < 4; p++)
                ldsm4(bf[2 * p][0], bf[2 * p][1], bf[2 * p + 1][0], bf[2 * p + 1][1],
                      bb + boff + (uint32_t)(p * 16 * LDP * 4) + kbb);
#pragma unroll
            for (int mt = 0; mt < 2; mt++)
#pragma unroll
                for (int nt = 0; nt < 8; nt++)
                    mma_tf32(acc[mt][nt][0], acc[mt][nt][1], acc[mt][nt][2], acc[mt][nt][3],
                             af[mt][0], af[mt][1], af[mt][2], af[mt][3],
                             bf[nt][0], bf[nt][1]);
        }
    }

    // ---- epilogue ----
#pragma unroll
    for (int mt = 0; mt < 2; mt++) {
#pragma unroll
        for (int half = 0; half < 2; half++) {
            const int m = m0 + warp_m + mt * 16 + r4 + half * 8;
            const int b_ = m >> 11;
            const int s_ = m & (SS - 1);
#pragma unroll
            for (int nt = 0; nt < 8; nt++) {
                const int col = warp_n + n0 + nt * 8 + 2 * c4;
                float ox = acc[mt][nt][half * 2 + 0] + bias[col];
                float oy = acc[mt][nt][half * 2 + 1] + bias[col + 1];
                if (out_mode == 1) {
                    const int h = col >> 6;
                    const int d = col & (HD - 1);
                    uint32_t* C = (uint32_t*)Cv;
                    *reinterpret_cast<uint2*>(
                        &C[(((size_t)(b_ * NH + h) * SS + s_) * HD) + d]) =
                        make_uint2(cvt_tf32(ox), cvt_tf32(oy));
                } else if (out_mode == 2) {
                    const int h = col >> 6;
                    const int d = col & (HD - 1);
                    uint32_t* C = (uint32_t*)Cv;
                    C[((size_t)(b_ * NH + h) * HD + d) * SS + s_]     = cvt_tf32(ox);
                    C[((size_t)(b_ * NH + h) * HD + d + 1) * SS + s_] = cvt_tf32(oy);
                } else {
                    float* C = (float*)Cv;
                    *reinterpret_cast<float2*>(&C[(size_t)m * EDIM + col]) = make_float2(ox, oy);
                }
            }
        }
    }
}

__global__ __launch_bounds__(256)
void gemm_qkv(const float* __restrict__ bq, const float* __restrict__ bk,
              const float* __restrict__ bv)
{
    const int z = blockIdx.z;
    const float* bias = (z == 0) ? bq : (z == 1) ? bk : bv;
    uint32_t* C = (z == 0) ? g_Q : (z == 1) ? g_K : g_V;
    gemm_body(g_Xt, g_Wt[z], bias, C, (z == 2) ? 2 : 1, blockIdx.x * GBM, blockIdx.y * GBN);
}

__global__ __launch_bounds__(256)
void gemm_out(const float* __restrict__ bo, float* __restrict__ C)
{
    gemm_body(g_ctx, g_Wt[3], bo, C, 0, blockIdx.x * GBM, blockIdx.y * GBN);
}

// ============================ flash attention: 32 q rows/warp, no-max softmax ============================
#define LKK 68
#define LVT 68
#define LPP 68
#define OFF_K0 0
#define OFF_V0 (64 * LKK)                  // 4352
#define OFF_K1 (OFF_V0 + 64 * LVT)         // 8704
#define OFF_V1 (OFF_K1 + 64 * LKK)         // 13056
#define OFF_P  (OFF_V1 + 64 * LVT)         // 17408
#define OFF_MD (OFF_P + 8 * 32 * LPP)      // 34816
#define ATT_SMEM ((OFF_MD + 128) * 4)      // 139776 bytes

__global__ __launch_bounds__(256, 1)
void attn_mma(const float* __restrict__ mask)
{
    extern __shared__ uint32_t sm[];
    const uint32_t sb = (uint32_t)__cvta_generic_to_shared(sm);
    float* madds = reinterpret_cast<float*>(sm + OFF_MD);

    const int bh = blockIdx.y;
    const int b_ = bh >> 4;
    const int h  = bh & (NH - 1);
    const int q0 = blockIdx.x * 256;
    const int tid = threadIdx.x;
    const int wid = tid >> 5;
    const int lane = tid & 31;
    const int r4 = lane >> 2;
    const int c4 = lane & 3;
    const int quad = lane >> 3;
    const int lrow = lane & 7;

    const int ks_off[2] = { OFF_K0, OFF_K1 };
    const int vs_off[2] = { OFF_V0, OFF_V1 };
    const int qrow = q0 + wid * 32;

    // Q fragments for 32 rows (2 m16 tiles) in registers for entire KV loop
    uint32_t aq[2][8][4];
    {
        const uint32_t* Qb = g_Q + ((size_t)bh * SS + qrow) * HD;
#pragma unroll
        for (int mt = 0; mt < 2; mt++)
#pragma unroll
            for (int ks = 0; ks < 8; ks++) {
                const uint32_t* R0 = &Qb[(size_t)(mt * 16 + r4) * HD + ks * 8 + c4];
                const uint32_t* R1 = &Qb[(size_t)(mt * 16 + r4 + 8) * HD + ks * 8 + c4];
                aq[mt][ks][0] = R0[0];
                aq[mt][ks][1] = R1[0];
                aq[mt][ks][2] = R0[4];
                aq[mt][ks][3] = R1[4];
            }
    }

    float ctx[2][8][4];
#pragma unroll
    for (int mt = 0; mt < 2; mt++)
#pragma unroll
        for (int nt = 0; nt < 8; nt++)
#pragma unroll
            for (int i = 0; i < 4; i++) ctx[mt][nt][i] = 0.f;
    // per-thread partial softmax denominators (reduced across lanes ONCE at the end)
    float lp[2][2];
    lp[0][0] = lp[0][1] = lp[1][0] = lp[1][1] = 0.f;
    const float scale = 0.125f;

    const int krow = tid >> 2;          // 0..63
    const int kcb = (tid & 3) * 16;     // 0..48

    auto stage = [&](int buf, int kt) {
        const uint32_t* Kp = g_K + ((size_t)bh * SS + kt + krow) * HD + kcb;
        uint32_t kd = sb + (uint32_t)((ks_off[buf] + krow * LKK + kcb) * 4);
#pragma unroll
        for (int i = 0; i < 4; i++) cp16(kd + i * 16, Kp + i * 4);
        const uint32_t* Vp = g_V + ((size_t)bh * HD + krow) * SS + kt + kcb;
        uint32_t vd = sb + (uint32_t)((vs_off[buf] + krow * LVT + kcb) * 4);
#pragma unroll
        for (int i = 0; i < 4; i++) cp16(vd + i * 16, Vp + i * 4);
        if (tid < 64)
            madds[buf * 64 + tid] = (1.0f - mask[b_ * SS + kt + tid]) * -10000.0f;
    };

    const uint32_t koff = (uint32_t)((((quad >> 1) * 8 + lrow) * LKK + (quad & 1) * 4) * 4);
    const uint32_t voff = (uint32_t)((((quad >> 1) * 8 + lrow) * LVT + (quad & 1) * 4) * 4);
    const uint32_t poff = (uint32_t)((((quad & 1) * 8 + lrow) * LPP + (quad >> 1) * 4) * 4);
    const uint32_t pwbase = sb + (uint32_t)((OFF_P + wid * 32 * LPP) * 4);
    uint32_t* Pw = sm + OFF_P + wid * 32 * LPP;

    stage(0, 0);
    cp_commit();

    const int NT = SS / 64;   // 32
    for (int t = 0; t < NT; t++) {
        const int cur = t & 1;
        cp_wait0();
        __syncthreads();
        if (t + 1 < NT) { stage(cur ^ 1, (t + 1) * 64); cp_commit(); }

        const uint32_t kb = sb + (uint32_t)(ks_off[cur] * 4);
        const uint32_t vb = sb + (uint32_t)(vs_off[cur] * 4);
        const float* madd = &madds[cur * 64];

        // ---- S = Q @ K^T (K fragments shared across both m-tiles) ----
        float sf[2][8][4];
#pragma unroll
        for (int mt = 0; mt < 2; mt++)
#pragma unroll
            for (int nt = 0; nt < 8; nt++)
                sf[mt][nt][0] = sf[mt][nt][1] = sf[mt][nt][2] = sf[mt][nt][3] = 0.f;
#pragma unroll
        for (int ks = 0; ks < 8; ks++) {
            uint32_t bf[8][2];
#pragma unroll
            for (int p = 0; p < 4; p++)
                ldsm4(bf[2 * p][0], bf[2 * p][1], bf[2 * p + 1][0], bf[2 * p + 1][1],
                      kb + koff + (uint32_t)(p * 16 * LKK * 4) + (uint32_t)(ks * 32));
#pragma unroll
            for (int mt = 0; mt < 2; mt++)
#pragma unroll
                for (int nt = 0; nt < 8; nt++)
                    mma_tf32(sf[mt][nt][0], sf[mt][nt][1], sf[mt][nt][2], sf[mt][nt][3],
                             aq[mt][ks][0], aq[mt][ks][1], aq[mt][ks][2], aq[mt][ks][3],
                             bf[nt][0], bf[nt][1]);
        }

        // ---- no-max softmax: p = exp(s*scale + madd); accumulate per-thread partials ----
#pragma unroll
        for (int mt = 0; mt < 2; mt++) {
            uint32_t* Pm = Pw + mt * 16 * LPP;
#pragma unroll
            for (int nt = 0; nt < 8; nt++) {
                float ma = madd[nt * 8 + 2 * c4];
                float mb = madd[nt * 8 + 2 * c4 + 1];
                float p0 = __expf(sf[mt][nt][0] * scale + ma);
                float p1 = __expf(sf[mt][nt][1] * scale + mb);
                float p2 = __expf(sf[mt][nt][2] * scale + ma);
                float p3 = __expf(sf[mt][nt][3] * scale + mb);
                lp[mt][0] += p0 + p1;
                lp[mt][1] += p2 + p3;
                *reinterpret_cast<uint2*>(&Pm[r4 * LPP + nt * 8 + 2 * c4]) =
                    make_uint2(cvt_tf32(p0), cvt_tf32(p1));
                *reinterpret_cast<uint2*>(&Pm[(r4 + 8) * LPP + nt * 8 + 2 * c4]) =
                    make_uint2(cvt_tf32(p2), cvt_tf32(p3));
            }
        }
        __syncwarp();

        // ---- ctx += P @ V (V fragments shared across both m-tiles) ----
#pragma unroll
        for (int ks2 = 0; ks2 < 8; ks2++) {
            uint32_t ap[2][4];
#pragma unroll
            for (int mt = 0; mt < 2; mt++)
                ldsm4(ap[mt][0], ap[mt][1], ap[mt][2], ap[mt][3],
                      pwbase + poff + (uint32_t)(mt * 16 * LPP * 4) + (uint32_t)(ks2 * 32));
            uint32_t vf[8][2];
#pragma unroll
            for (int p = 0; p < 4; p++)
                ldsm4(vf[2 * p][0], vf[2 * p][1], vf[2 * p + 1][0], vf[2 * p + 1][1],
                      vb + voff + (uint32_t)(p * 16 * LVT * 4) + (uint32_t)(ks2 * 32));
#pragma unroll
            for (int mt = 0; mt < 2; mt++)
#pragma unroll
                for (int nt2 = 0; nt2 < 8; nt2++)
                    mma_tf32(ctx[mt][nt2][0], ctx[mt][nt2][1], ctx[mt][nt2][2], ctx[mt][nt2][3],
                             ap[mt][0], ap[mt][1], ap[mt][2], ap[mt][3],
                             vf[nt2][0], vf[nt2][1]);
        }
        __syncwarp();
    }

    // ---- final denominator reduction (once) + epilogue ----
#pragma unroll
    for (int mt = 0; mt < 2; mt++) {
        float l0 = lp[mt][0], l1 = lp[mt][1];
        l0 += __shfl_xor_sync(0xffffffff, l0, 1);
        l0 += __shfl_xor_sync(0xffffffff, l0, 2);
        l1 += __shfl_xor_sync(0xffffffff, l1, 1);
        l1 += __shfl_xor_sync(0xffffffff, l1, 2);
        float inv0 = 1.0f / l0;
        float inv1 = 1.0f / l1;
        const int sq0 = qrow + mt * 16 + r4;
        uint32_t* C0 = g_ctx + ((size_t)(b_ * SS + sq0) * EDIM) + h * HD;
        uint32_t* C1 = g_ctx + ((size_t)(b_ * SS + sq0 + 8) * EDIM) + h * HD;
#pragma unroll
        for (int nt2 = 0; nt2 < 8; nt2++) {
            const int col = nt2 * 8 + 2 * c4;
            *reinterpret_cast<uint2*>(&C0[col]) =
                make_uint2(cvt_tf32(ctx[mt][nt2][0] * inv0), cvt_tf32(ctx[mt][nt2][1] * inv0));
            *reinterpret_cast<uint2*>(&C1[col]) =
                make_uint2(cvt_tf32(ctx[mt][nt2][2] * inv1), cvt_tf32(ctx[mt][nt2][3] * inv1));
        }
    }
}

// ============================ launch ============================
extern "C" void kernel_launch(void* const* d_in, const int* in_sizes, int n_in,
                              void* d_out, int out_size)
{
    const float* X    = (const float*)d_in[0];
    const float* mask = (const float*)d_in[1];
    const float* Wq   = (const float*)d_in[2];
    const float* bq   = (const float*)d_in[3];
    const float* Wk   = (const float*)d_in[4];
    const float* bk   = (const float*)d_in[5];
    const float* Wv   = (const float*)d_in[6];
    const float* bv   = (const float*)d_in[7];
    const float* Wo   = (const float*)d_in[8];
    const float* bo   = (const float*)d_in[9];
    float* out = (float*)d_out;

    const int gemm_smem = 4 * TILE_U32 * 4;   // 73728
    cudaFuncSetAttribute(gemm_qkv, cudaFuncAttributeMaxDynamicSharedMemorySize, gemm_smem);
    cudaFuncSetAttribute(gemm_out, cudaFuncAttributeMaxDynamicSharedMemorySize, gemm_smem);
    cudaFuncSetAttribute(attn_mma, cudaFuncAttributeMaxDynamicSharedMemorySize, ATT_SMEM);

    prep_x<<<MTOT * EDIM / 1024, 256>>>(X);

    dim3 tgrid(32, 32, 4), tblk(32, 8);
    transpose4<<<tgrid, tblk>>>(Wq, Wk, Wv, Wo);

    dim3 qkvgrid(MTOT / GBM, EDIM / GBN, 3);   // 32 x 8 x 3
    gemm_qkv<<<qkvgrid, 256, gemm_smem>>>(bq, bk, bv);

    dim3 agrid(SS / 256, BB * NH);             // 8 x 32
    attn_mma<<<agrid, 256, ATT_SMEM>>>(mask);

    dim3 ogrid(MTOT / GBM, EDIM / GBN);        // 32 x 8
    gemm_out<<<ogrid, 256, gemm_smem>>>(bo, out);
}

// round 13
// speedup vs baseline: 2.7083x; 2.0282x over previous
#include <cuda_runtime.h>
#include <cuda_fp16.h>
#include <math.h>
#include <cstdint>

#define EDIM 1024
#define NH   16
#define HD   64
#define BB   2
#define SS   2048
#define MTOT (BB*SS)   // 4096

// Scratch (fp16)
__device__ __half g_Xt[MTOT*EDIM];
__device__ __half g_Q[MTOT*EDIM];
__device__ __half g_K[MTOT*EDIM];
__device__ __half g_V[MTOT*EDIM];     // TRANSPOSED: [b][h][d][s]
__device__ __half g_ctx[MTOT*EDIM];
__device__ __half g_Wt[4][EDIM*EDIM]; // transposed weights [n][k]

// pack two floats -> half2 (lo in low half)
__device__ __forceinline__ uint32_t cvt_h2(float lo, float hi) {
    uint32_t r; asm("cvt.rn.f16x2.f32 %0,%1,%2;" : "=r"(r) : "f"(hi), "f"(lo));
    return r;
}
__device__ __forceinline__ void mma_fp16(float& d0, float& d1, float& d2, float& d3,
                                         uint32_t a0, uint32_t a1, uint32_t a2, uint32_t a3,
                                         uint32_t b0, uint32_t b1) {
    asm volatile(
        "mma.sync.aligned.m16n8k16.row.col.f32.f16.f16.f32 "
        "{%0,%1,%2,%3},{%4,%5,%6,%7},{%8,%9},{%0,%1,%2,%3};"
        : "+f"(d0), "+f"(d1), "+f"(d2), "+f"(d3)
        : "r"(a0), "r"(a1), "r"(a2), "r"(a3), "r"(b0), "r"(b1));
}
__device__ __forceinline__ void ldsm4(uint32_t& r0, uint32_t& r1, uint32_t& r2, uint32_t& r3,
                                      uint32_t addr) {
    asm volatile("ldmatrix.sync.aligned.m8n8.x4.shared.b16 {%0,%1,%2,%3}, [%4];"
                 : "=r"(r0), "=r"(r1), "=r"(r2), "=r"(r3) : "r"(addr));
}
__device__ __forceinline__ void cp16(uint32_t dst, const void* src) {
    asm volatile("cp.async.cg.shared.global [%0], [%1], 16;" :: "r"(dst), "l"(src));
}
__device__ __forceinline__ void cp_commit() { asm volatile("cp.async.commit_group;"); }
__device__ __forceinline__ void cp_wait0()  { asm volatile("cp.async.wait_group 0;" ::: "memory"); }

// ============================ X -> fp16 prep ============================
__global__ __launch_bounds__(256)
void prep_x(const float* __restrict__ X)
{
    size_t i = ((size_t)blockIdx.x * 256 + threadIdx.x) * 4;
    float4 v = *reinterpret_cast<const float4*>(&X[i]);
    uint2 o;
    o.x = cvt_h2(v.x, v.y);
    o.y = cvt_h2(v.z, v.w);
    *reinterpret_cast<uint2*>(&g_Xt[i]) = o;
}

// ============================ fused transpose (fp16 out) ============================
__global__ __launch_bounds__(256)
void transpose4(const float* __restrict__ w0, const float* __restrict__ w1,
                const float* __restrict__ w2, const float* __restrict__ w3)
{
    const float* in = (blockIdx.z == 0) ? w0 : (blockIdx.z == 1) ? w1 : (blockIdx.z == 2) ? w2 : w3;
    __half* out = g_Wt[blockIdx.z];
    __shared__ float t[32][33];
    int x = blockIdx.x * 32 + threadIdx.x;
    int y = blockIdx.y * 32 + threadIdx.y;
#pragma unroll
    for (int j = 0; j < 32; j += 8)
        t[threadIdx.y + j][threadIdx.x] = in[(size_t)(y + j) * EDIM + x];
    __syncthreads();
    x = blockIdx.y * 32 + threadIdx.x;
    y = blockIdx.x * 32 + threadIdx.y;
#pragma unroll
    for (int j = 0; j < 32; j += 8)
        out[(size_t)(y + j) * EDIM + x] = __float2half_rn(t[threadIdx.x][threadIdx.y + j]);
}

// ============================ fp16 mma.sync GEMM ============================
#define GBM 128
#define GBN 128
#define GBK 32
#define LDA 40                       // halves per SMEM row (32 data + 8 pad) = 80B
#define TILE_BYTES (128 * LDA * 2)   // 10240
#define GEMM_SMEM (4 * TILE_BYTES)   // 40960

// out_mode: 0 = float row-major; 1 = fp16 [b][h][s][d]; 2 = fp16 [b][h][d][s]
__device__ __forceinline__ void gemm_body(const __half* __restrict__ A,
                                          const __half* __restrict__ Wt,
                                          const float* __restrict__ bias,
                                          void* __restrict__ Cv,
                                          int out_mode, int m0, int n0)
{
    extern __shared__ char smc[];
    const uint32_t sb = (uint32_t)__cvta_generic_to_shared(smc);

    const int tid = threadIdx.x;
    const int wid = tid >> 5;
    const int lane = tid & 31;
    const int warp_m = (wid & 3) * 32;
    const int warp_n = (wid >> 2) * 64;
    const int r4 = lane >> 2;
    const int c4 = lane & 3;
    const int quad = lane >> 3;
    const int lrow = lane & 7;

    float acc[2][8][4];
#pragma unroll
    for (int mt = 0; mt < 2; mt++)
#pragma unroll
        for (int nt = 0; nt < 8; nt++)
#pragma unroll
            for (int i = 0; i < 4; i++) acc[mt][nt][i] = 0.f;

    const int sr = tid >> 1;             // row 0..127
    const int sch = (tid & 1) * 16;      // half col base
    auto stage = [&](int buf, int k0) {
        uint32_t ad = sb + (uint32_t)(buf * 2 * TILE_BYTES + sr * (LDA * 2) + sch * 2);
        const __half* Ap = &A[(size_t)(m0 + sr) * EDIM + k0 + sch];
        cp16(ad, Ap); cp16(ad + 16, Ap + 8);
        uint32_t bd = ad + (uint32_t)TILE_BYTES;
        const __half* Bp = &Wt[(size_t)(n0 + sr) * EDIM + k0 + sch];
        cp16(bd, Bp); cp16(bd + 16, Bp + 8);
    };

    const uint32_t aoff = (uint32_t)(((warp_m + (quad & 1) * 8 + lrow) * LDA + (quad >> 1) * 8) * 2);
    const uint32_t boff = (uint32_t)(((warp_n + (quad >> 1) * 8 + lrow) * LDA + (quad & 1) * 8) * 2);

    stage(0, 0);
    cp_commit();

    const int NCHUNK = EDIM / GBK;   // 32
    for (int c = 0; c < NCHUNK; c++) {
        const int cur = c & 1;
        cp_wait0();
        __syncthreads();
        if (c + 1 < NCHUNK) { stage(cur ^ 1, (c + 1) * GBK); cp_commit(); }

        const uint32_t ab = sb + (uint32_t)(cur * 2 * TILE_BYTES);
        const uint32_t bb = ab + (uint32_t)TILE_BYTES;
#pragma unroll
        for (int ks = 0; ks < 2; ks++) {
            const uint32_t kbb = (uint32_t)(ks * 32);   // 16 halves
            uint32_t af[2][4];
#pragma unroll
            for (int mt = 0; mt < 2; mt++)
                ldsm4(af[mt][0], af[mt][1], af[mt][2], af[mt][3],
                      ab + aoff + (uint32_t)(mt * 16 * LDA * 2) + kbb);
            uint32_t bf[8][2];
#pragma unroll
            for (int p = 0; p < 4; p++)
                ldsm4(bf[2 * p][0], bf[2 * p][1], bf[2 * p + 1][0], bf[2 * p + 1][1],
                      bb + boff + (uint32_t)(p * 16 * LDA * 2) + kbb);
#pragma unroll
            for (int mt = 0; mt < 2; mt++)
#pragma unroll
                for (int nt = 0; nt < 8; nt++)
                    mma_fp16(acc[mt][nt][0], acc[mt][nt][1], acc[mt][nt][2], acc[mt][nt][3],
                             af[mt][0], af[mt][1], af[mt][2], af[mt][3],
                             bf[nt][0], bf[nt][1]);
        }
    }

    // ---- epilogue ----
#pragma unroll
    for (int mt = 0; mt < 2; mt++) {
#pragma unroll
        for (int half = 0; half < 2; half++) {
            const int m = m0 + warp_m + mt * 16 + r4 + half * 8;
            const int b_ = m >> 11;
            const int s_ = m & (SS - 1);
#pragma unroll
            for (int nt = 0; nt < 8; nt++) {
                const int col = warp_n + n0 + nt * 8 + 2 * c4;
                float ox = acc[mt][nt][half * 2 + 0] + bias[col];
                float oy = acc[mt][nt][half * 2 + 1] + bias[col + 1];
                if (out_mode == 1) {
                    const int h = col >> 6;
                    const int d = col & (HD - 1);
                    __half* C = (__half*)Cv;
                    *reinterpret_cast<uint32_t*>(
                        &C[(((size_t)(b_ * NH + h) * SS + s_) * HD) + d]) = cvt_h2(ox, oy);
                } else if (out_mode == 2) {
                    const int h = col >> 6;
                    const int d = col & (HD - 1);
                    __half* C = (__half*)Cv;
                    C[((size_t)(b_ * NH + h) * HD + d) * SS + s_]     = __float2half_rn(ox);
                    C[((size_t)(b_ * NH + h) * HD + d + 1) * SS + s_] = __float2half_rn(oy);
                } else {
                    float* C = (float*)Cv;
                    *reinterpret_cast<float2*>(&C[(size_t)m * EDIM + col]) = make_float2(ox, oy);
                }
            }
        }
    }
}

__global__ __launch_bounds__(256)
void gemm_qkv(const float* __restrict__ bq, const float* __restrict__ bk,
              const float* __restrict__ bv)
{
    const int z = blockIdx.z;
    const float* bias = (z == 0) ? bq : (z == 1) ? bk : bv;
    __half* C = (z == 0) ? g_Q : (z == 1) ? g_K : g_V;
    gemm_body(g_Xt, g_Wt[z], bias, C, (z == 2) ? 2 : 1, blockIdx.x * GBM, blockIdx.y * GBN);
}

__global__ __launch_bounds__(256)
void gemm_out(const float* __restrict__ bo, float* __restrict__ C)
{
    gemm_body(g_ctx, g_Wt[3], bo, C, 0, blockIdx.x * GBM, blockIdx.y * GBN);
}

// ============================ flash attention fp16: 32 q rows/warp, no-max softmax ============================
#define LKH 72                        // halves per SMEM row (64 + 8 pad) = 144B
#define KT_BYTES (64 * LKH * 2)       // 9216
#define OFF_K0 0
#define OFF_V0 KT_BYTES               // 9216
#define OFF_K1 (2 * KT_BYTES)         // 18432
#define OFF_V1 (3 * KT_BYTES)         // 27648
#define OFF_P  (4 * KT_BYTES)         // 36864
#define PW_BYTES (32 * LKH * 2)       // 4608
#define OFF_MD (OFF_P + 8 * PW_BYTES) // 73728 (bytes; float mask after)
#define ATT_SMEM (OFF_MD + 512)       // 74240

__global__ __launch_bounds__(256, 1)
void attn_mma(const float* __restrict__ mask)
{
    extern __shared__ char smc[];
    const uint32_t sb = (uint32_t)__cvta_generic_to_shared(smc);
    float* madds = reinterpret_cast<float*>(smc + OFF_MD);

    const int bh = blockIdx.y;
    const int b_ = bh >> 4;
    const int h  = bh & (NH - 1);
    const int q0 = blockIdx.x * 256;
    const int tid = threadIdx.x;
    const int wid = tid >> 5;
    const int lane = tid & 31;
    const int r4 = lane >> 2;
    const int c4 = lane & 3;
    const int quad = lane >> 3;
    const int lrow = lane & 7;

    const int qrow = q0 + wid * 32;

    // Q fragments: 2 m16 tiles x 4 k16-steps x 4 regs (half2 pairs)
    uint32_t aq[2][4][4];
    {
        const uint32_t* Q32 = reinterpret_cast<const uint32_t*>(g_Q + ((size_t)bh * SS + qrow) * HD);
#pragma unroll
        for (int mt = 0; mt < 2; mt++)
#pragma unroll
            for (int ks = 0; ks < 4; ks++) {
                const int base0 = (mt * 16 + r4) * 32 + ks * 8 + c4;       // u32 index (row, k-lo)
                const int base1 = (mt * 16 + r4 + 8) * 32 + ks * 8 + c4;
                aq[mt][ks][0] = Q32[base0];
                aq[mt][ks][1] = Q32[base1];
                aq[mt][ks][2] = Q32[base0 + 4];
                aq[mt][ks][3] = Q32[base1 + 4];
            }
    }

    float ctx[2][8][4];
#pragma unroll
    for (int mt = 0; mt < 2; mt++)
#pragma unroll
        for (int nt = 0; nt < 8; nt++)
#pragma unroll
            for (int i = 0; i < 4; i++) ctx[mt][nt][i] = 0.f;
    float lp[2][2];
    lp[0][0] = lp[0][1] = lp[1][0] = lp[1][1] = 0.f;
    const float scale = 0.125f;

    const int krow = tid >> 2;          // 0..63
    const int kcb = (tid & 3) * 16;     // half col base

    auto stage = [&](int buf, int kt) {
        const __half* Kp = g_K + ((size_t)bh * SS + kt + krow) * HD + kcb;
        uint32_t kd = sb + (uint32_t)((buf ? OFF_K1 : OFF_K0) + krow * (LKH * 2) + kcb * 2);
        cp16(kd, Kp); cp16(kd + 16, Kp + 8);
        const __half* Vp = g_V + ((size_t)bh * HD + krow) * SS + kt + kcb;
        uint32_t vd = sb + (uint32_t)((buf ? OFF_V1 : OFF_V0) + krow * (LKH * 2) + kcb * 2);
        cp16(vd, Vp); cp16(vd + 16, Vp + 8);
        if (tid < 64)
            madds[buf * 64 + tid] = (1.0f - mask[b_ * SS + kt + tid]) * -10000.0f;
    };

    // B-fragment pattern (K and V tiles), A-fragment pattern (P tile)
    const uint32_t boffp = (uint32_t)(((quad >> 1) * 8 + lrow) * (LKH * 2) + (quad & 1) * 16);
    const uint32_t poff  = (uint32_t)(((quad & 1) * 8 + lrow) * (LKH * 2) + (quad >> 1) * 16);
    const uint32_t pwbase = sb + (uint32_t)(OFF_P + wid * PW_BYTES);
    char* Pw = smc + OFF_P + wid * PW_BYTES;

    stage(0, 0);
    cp_commit();

    const int NT = SS / 64;   // 32
    for (int t = 0; t < NT; t++) {
        const int cur = t & 1;
        cp_wait0();
        __syncthreads();
        if (t + 1 < NT) { stage(cur ^ 1, (t + 1) * 64); cp_commit(); }

        const uint32_t kb = sb + (uint32_t)(cur ? OFF_K1 : OFF_K0);
        const uint32_t vb = sb + (uint32_t)(cur ? OFF_V1 : OFF_V0);
        const float* madd = &madds[cur * 64];

        // ---- S = Q @ K^T ----
        float sf[2][8][4];
#pragma unroll
        for (int mt = 0; mt < 2; mt++)
#pragma unroll
            for (int nt = 0; nt < 8; nt++)
                sf[mt][nt][0] = sf[mt][nt][1] = sf[mt][nt][2] = sf[mt][nt][3] = 0.f;
#pragma unroll
        for (int ks = 0; ks < 4; ks++) {
            uint32_t bf[8][2];
#pragma unroll
            for (int p = 0; p < 4; p++)
                ldsm4(bf[2 * p][0], bf[2 * p][1], bf[2 * p + 1][0], bf[2 * p + 1][1],
                      kb + boffp + (uint32_t)(p * 16 * LKH * 2) + (uint32_t)(ks * 32));
#pragma unroll
            for (int mt = 0; mt < 2; mt++)
#pragma unroll
                for (int nt = 0; nt < 8; nt++)
                    mma_fp16(sf[mt][nt][0], sf[mt][nt][1], sf[mt][nt][2], sf[mt][nt][3],
                             aq[mt][ks][0], aq[mt][ks][1], aq[mt][ks][2], aq[mt][ks][3],
                             bf[nt][0], bf[nt][1]);
        }

        // ---- no-max softmax: p = exp(s*scale + madd); per-thread partial sums ----
#pragma unroll
        for (int mt = 0; mt < 2; mt++) {
            char* Pm = Pw + mt * 16 * LKH * 2;
#pragma unroll
            for (int nt = 0; nt < 8; nt++) {
                float ma = madd[nt * 8 + 2 * c4];
                float mb = madd[nt * 8 + 2 * c4 + 1];
                float p0 = __expf(sf[mt][nt][0] * scale + ma);
                float p1 = __expf(sf[mt][nt][1] * scale + mb);
                float p2 = __expf(sf[mt][nt][2] * scale + ma);
                float p3 = __expf(sf[mt][nt][3] * scale + mb);
                lp[mt][0] += p0 + p1;
                lp[mt][1] += p2 + p3;
                *reinterpret_cast<uint32_t*>(Pm + (r4 * LKH + nt * 8 + 2 * c4) * 2) = cvt_h2(p0, p1);
                *reinterpret_cast<uint32_t*>(Pm + ((r4 + 8) * LKH + nt * 8 + 2 * c4) * 2) = cvt_h2(p2, p3);
            }
        }
        __syncwarp();

        // ---- ctx += P @ V (V transposed tile: [d][key], k-major B) ----
#pragma unroll
        for (int ks2 = 0; ks2 < 4; ks2++) {
            uint32_t ap[2][4];
#pragma unroll
            for (int mt = 0; mt < 2; mt++)
                ldsm4(ap[mt][0], ap[mt][1], ap[mt][2], ap[mt][3],
                      pwbase + poff + (uint32_t)(mt * 16 * LKH * 2) + (uint32_t)(ks2 * 32));
            uint32_t vf[8][2];
#pragma unroll
            for (int p = 0; p < 4; p++)
                ldsm4(vf[2 * p][0], vf[2 * p][1], vf[2 * p + 1][0], vf[2 * p + 1][1],
                      vb + boffp + (uint32_t)(p * 16 * LKH * 2) + (uint32_t)(ks2 * 32));
#pragma unroll
            for (int mt = 0; mt < 2; mt++)
#pragma unroll
                for (int nt2 = 0; nt2 < 8; nt2++)
                    mma_fp16(ctx[mt][nt2][0], ctx[mt][nt2][1], ctx[mt][nt2][2], ctx[mt][nt2][3],
                             ap[mt][0], ap[mt][1], ap[mt][2], ap[mt][3],
                             vf[nt2][0], vf[nt2][1]);
        }
        __syncwarp();
    }

    // ---- final denominator reduction + epilogue (fp16 ctx out) ----
#pragma unroll
    for (int mt = 0; mt < 2; mt++) {
        float l0 = lp[mt][0], l1 = lp[mt][1];
        l0 += __shfl_xor_sync(0xffffffff, l0, 1);
        l0 += __shfl_xor_sync(0xffffffff, l0, 2);
        l1 += __shfl_xor_sync(0xffffffff, l1, 1);
        l1 += __shfl_xor_sync(0xffffffff, l1, 2);
        float inv0 = 1.0f / l0;
        float inv1 = 1.0f / l1;
        const int sq0 = qrow + mt * 16 + r4;
        __half* C0 = g_ctx + ((size_t)(b_ * SS + sq0) * EDIM) + h * HD;
        __half* C1 = g_ctx + ((size_t)(b_ * SS + sq0 + 8) * EDIM) + h * HD;
#pragma unroll
        for (int nt2 = 0; nt2 < 8; nt2++) {
            const int col = nt2 * 8 + 2 * c4;
            *reinterpret_cast<uint32_t*>(&C0[col]) =
                cvt_h2(ctx[mt][nt2][0] * inv0, ctx[mt][nt2][1] * inv0);
            *reinterpret_cast<uint32_t*>(&C1[col]) =
                cvt_h2(ctx[mt][nt2][2] * inv1, ctx[mt][nt2][3] * inv1);
        }
    }
}

// ============================ launch ============================
extern "C" void kernel_launch(void* const* d_in, const int* in_sizes, int n_in,
                              void* d_out, int out_size)
{
    const float* X    = (const float*)d_in[0];
    const float* mask = (const float*)d_in[1];
    const float* Wq   = (const float*)d_in[2];
    const float* bq   = (const float*)d_in[3];
    const float* Wk   = (const float*)d_in[4];
    const float* bk   = (const float*)d_in[5];
    const float* Wv   = (const float*)d_in[6];
    const float* bv   = (const float*)d_in[7];
    const float* Wo   = (const float*)d_in[8];
    const float* bo   = (const float*)d_in[9];
    float* out = (float*)d_out;

    cudaFuncSetAttribute(gemm_qkv, cudaFuncAttributeMaxDynamicSharedMemorySize, GEMM_SMEM);
    cudaFuncSetAttribute(gemm_out, cudaFuncAttributeMaxDynamicSharedMemorySize, GEMM_SMEM);
    cudaFuncSetAttribute(attn_mma, cudaFuncAttributeMaxDynamicSharedMemorySize, ATT_SMEM);

    prep_x<<<MTOT * EDIM / 1024, 256>>>(X);

    dim3 tgrid(32, 32, 4), tblk(32, 8);
    transpose4<<<tgrid, tblk>>>(Wq, Wk, Wv, Wo);

    dim3 qkvgrid(MTOT / GBM, EDIM / GBN, 3);   // 32 x 8 x 3
    gemm_qkv<<<qkvgrid, 256, GEMM_SMEM>>>(bq, bk, bv);

    dim3 agrid(SS / 256, BB * NH);             // 8 x 32
    attn_mma<<<agrid, 256, ATT_SMEM>>>(mask);

    dim3 ogrid(MTOT / GBM, EDIM / GBN);        // 32 x 8
    gemm_out<<<ogrid, 256, GEMM_SMEM>>>(bo, out);
}

// round 14
// speedup vs baseline: 2.8231x; 1.0424x over previous
#include <cuda_runtime.h>
#include <cuda_fp16.h>
#include <math.h>
#include <cstdint>

#define EDIM 1024
#define NH   16
#define HD   64
#define BB   2
#define SS   2048
#define MTOT (BB*SS)   // 4096

// Scratch (fp16)
__device__ __half g_Xt[MTOT*EDIM];
__device__ __half g_Q[MTOT*EDIM];
__device__ __half g_K[MTOT*EDIM];
__device__ __half g_V[MTOT*EDIM];     // TRANSPOSED: [b][h][d][s]
__device__ __half g_ctx[MTOT*EDIM];
__device__ __half g_Wt[4][EDIM*EDIM]; // transposed weights [n][k]

// pack two floats -> half2 (lo in low half)
__device__ __forceinline__ uint32_t cvt_h2(float lo, float hi) {
    uint32_t r; asm("cvt.rn.f16x2.f32 %0,%1,%2;" : "=r"(r) : "f"(hi), "f"(lo));
    return r;
}
__device__ __forceinline__ void mma_fp16(float& d0, float& d1, float& d2, float& d3,
                                         uint32_t a0, uint32_t a1, uint32_t a2, uint32_t a3,
                                         uint32_t b0, uint32_t b1) {
    asm volatile(
        "mma.sync.aligned.m16n8k16.row.col.f32.f16.f16.f32 "
        "{%0,%1,%2,%3},{%4,%5,%6,%7},{%8,%9},{%0,%1,%2,%3};"
        : "+f"(d0), "+f"(d1), "+f"(d2), "+f"(d3)
        : "r"(a0), "r"(a1), "r"(a2), "r"(a3), "r"(b0), "r"(b1));
}
__device__ __forceinline__ void ldsm4(uint32_t& r0, uint32_t& r1, uint32_t& r2, uint32_t& r3,
                                      uint32_t addr) {
    asm volatile("ldmatrix.sync.aligned.m8n8.x4.shared.b16 {%0,%1,%2,%3}, [%4];"
                 : "=r"(r0), "=r"(r1), "=r"(r2), "=r"(r3) : "r"(addr));
}
__device__ __forceinline__ void cp16(uint32_t dst, const void* src) {
    asm volatile("cp.async.cg.shared.global [%0], [%1], 16;" :: "r"(dst), "l"(src));
}
__device__ __forceinline__ void cp_commit() { asm volatile("cp.async.commit_group;"); }
__device__ __forceinline__ void cp_wait0()  { asm volatile("cp.async.wait_group 0;" ::: "memory"); }

// ============================ X -> fp16 prep ============================
__global__ __launch_bounds__(256)
void prep_x(const float* __restrict__ X)
{
    size_t i = ((size_t)blockIdx.x * 256 + threadIdx.x) * 4;
    float4 v = *reinterpret_cast<const float4*>(&X[i]);
    uint2 o;
    o.x = cvt_h2(v.x, v.y);
    o.y = cvt_h2(v.z, v.w);
    *reinterpret_cast<uint2*>(&g_Xt[i]) = o;
}

// ============================ fused transpose (fp16 out) ============================
__global__ __launch_bounds__(256)
void transpose4(const float* __restrict__ w0, const float* __restrict__ w1,
                const float* __restrict__ w2, const float* __restrict__ w3)
{
    const float* in = (blockIdx.z == 0) ? w0 : (blockIdx.z == 1) ? w1 : (blockIdx.z == 2) ? w2 : w3;
    __half* out = g_Wt[blockIdx.z];
    __shared__ float t[32][33];
    int x = blockIdx.x * 32 + threadIdx.x;
    int y = blockIdx.y * 32 + threadIdx.y;
#pragma unroll
    for (int j = 0; j < 32; j += 8)
        t[threadIdx.y + j][threadIdx.x] = in[(size_t)(y + j) * EDIM + x];
    __syncthreads();
    x = blockIdx.y * 32 + threadIdx.x;
    y = blockIdx.x * 32 + threadIdx.y;
#pragma unroll
    for (int j = 0; j < 32; j += 8)
        out[(size_t)(y + j) * EDIM + x] = __float2half_rn(t[threadIdx.x][threadIdx.y + j]);
}

// ============================ fp16 mma.sync GEMM ============================
#define GBM 128
#define GBN 128
#define GBK 32
#define LDA 40                       // halves per SMEM row (32 data + 8 pad) = 80B
#define TILE_BYTES (128 * LDA * 2)   // 10240
#define GEMM_SMEM (4 * TILE_BYTES)   // 40960

// out_mode: 0 = float row-major; 1 = fp16 [b][h][s][d]; 2 = fp16 [b][h][d][s]
__device__ __forceinline__ void gemm_body(const __half* __restrict__ A,
                                          const __half* __restrict__ Wt,
                                          const float* __restrict__ bias,
                                          void* __restrict__ Cv,
                                          int out_mode, int m0, int n0)
{
    extern __shared__ char smc[];
    const uint32_t sb = (uint32_t)__cvta_generic_to_shared(smc);

    const int tid = threadIdx.x;
    const int wid = tid >> 5;
    const int lane = tid & 31;
    const int warp_m = (wid & 3) * 32;
    const int warp_n = (wid >> 2) * 64;
    const int r4 = lane >> 2;
    const int c4 = lane & 3;
    const int quad = lane >> 3;
    const int lrow = lane & 7;

    float acc[2][8][4];
#pragma unroll
    for (int mt = 0; mt < 2; mt++)
#pragma unroll
        for (int nt = 0; nt < 8; nt++)
#pragma unroll
            for (int i = 0; i < 4; i++) acc[mt][nt][i] = 0.f;

    const int sr = tid >> 1;             // row 0..127
    const int sch = (tid & 1) * 16;      // half col base
    auto stage = [&](int buf, int k0) {
        uint32_t ad = sb + (uint32_t)(buf * 2 * TILE_BYTES + sr * (LDA * 2) + sch * 2);
        const __half* Ap = &A[(size_t)(m0 + sr) * EDIM + k0 + sch];
        cp16(ad, Ap); cp16(ad + 16, Ap + 8);
        uint32_t bd = ad + (uint32_t)TILE_BYTES;
        const __half* Bp = &Wt[(size_t)(n0 + sr) * EDIM + k0 + sch];
        cp16(bd, Bp); cp16(bd + 16, Bp + 8);
    };

    const uint32_t aoff = (uint32_t)(((warp_m + (quad & 1) * 8 + lrow) * LDA + (quad >> 1) * 8) * 2);
    const uint32_t boff = (uint32_t)(((warp_n + (quad >> 1) * 8 + lrow) * LDA + (quad & 1) * 8) * 2);

    stage(0, 0);
    cp_commit();

    const int NCHUNK = EDIM / GBK;   // 32
    for (int c = 0; c < NCHUNK; c++) {
        const int cur = c & 1;
        cp_wait0();
        __syncthreads();
        if (c + 1 < NCHUNK) { stage(cur ^ 1, (c + 1) * GBK); cp_commit(); }

        const uint32_t ab = sb + (uint32_t)(cur * 2 * TILE_BYTES);
        const uint32_t bb = ab + (uint32_t)TILE_BYTES;
#pragma unroll
        for (int ks = 0; ks < 2; ks++) {
            const uint32_t kbb = (uint32_t)(ks * 32);   // 16 halves
            uint32_t af[2][4];
#pragma unroll
            for (int mt = 0; mt < 2; mt++)
                ldsm4(af[mt][0], af[mt][1], af[mt][2], af[mt][3],
                      ab + aoff + (uint32_t)(mt * 16 * LDA * 2) + kbb);
            uint32_t bf[8][2];
#pragma unroll
            for (int p = 0; p < 4; p++)
                ldsm4(bf[2 * p][0], bf[2 * p][1], bf[2 * p + 1][0], bf[2 * p + 1][1],
                      bb + boff + (uint32_t)(p * 16 * LDA * 2) + kbb);
#pragma unroll
            for (int mt = 0; mt < 2; mt++)
#pragma unroll
                for (int nt = 0; nt < 8; nt++)
                    mma_fp16(acc[mt][nt][0], acc[mt][nt][1], acc[mt][nt][2], acc[mt][nt][3],
                             af[mt][0], af[mt][1], af[mt][2], af[mt][3],
                             bf[nt][0], bf[nt][1]);
        }
    }

    // ---- epilogue ----
#pragma unroll
    for (int mt = 0; mt < 2; mt++) {
#pragma unroll
        for (int half = 0; half < 2; half++) {
            const int m = m0 + warp_m + mt * 16 + r4 + half * 8;
            const int b_ = m >> 11;
            const int s_ = m & (SS - 1);
#pragma unroll
            for (int nt = 0; nt < 8; nt++) {
                const int col = warp_n + n0 + nt * 8 + 2 * c4;
                float ox = acc[mt][nt][half * 2 + 0] + bias[col];
                float oy = acc[mt][nt][half * 2 + 1] + bias[col + 1];
                if (out_mode == 1) {
                    const int h = col >> 6;
                    const int d = col & (HD - 1);
                    __half* C = (__half*)Cv;
                    *reinterpret_cast<uint32_t*>(
                        &C[(((size_t)(b_ * NH + h) * SS + s_) * HD) + d]) = cvt_h2(ox, oy);
                } else if (out_mode == 2) {
                    const int h = col >> 6;
                    const int d = col & (HD - 1);
                    __half* C = (__half*)Cv;
                    C[((size_t)(b_ * NH + h) * HD + d) * SS + s_]     = __float2half_rn(ox);
                    C[((size_t)(b_ * NH + h) * HD + d + 1) * SS + s_] = __float2half_rn(oy);
                } else {
                    float* C = (float*)Cv;
                    *reinterpret_cast<float2*>(&C[(size_t)m * EDIM + col]) = make_float2(ox, oy);
                }
            }
        }
    }
}

__global__ __launch_bounds__(256, 2)
void gemm_qkv(const float* __restrict__ bq, const float* __restrict__ bk,
              const float* __restrict__ bv)
{
    const int z = blockIdx.z;
    const float* bias = (z == 0) ? bq : (z == 1) ? bk : bv;
    __half* C = (z == 0) ? g_Q : (z == 1) ? g_K : g_V;
    gemm_body(g_Xt, g_Wt[z], bias, C, (z == 2) ? 2 : 1, blockIdx.x * GBM, blockIdx.y * GBN);
}

__global__ __launch_bounds__(256, 2)
void gemm_out(const float* __restrict__ bo, float* __restrict__ C)
{
    gemm_body(g_ctx, g_Wt[3], bo, C, 0, blockIdx.x * GBM, blockIdx.y * GBN);
}

// ============================ flash attention fp16: 16 q rows/warp, 2 CTAs/SM ============================
#define LKH 72                        // halves per SMEM row (64 + 8 pad) = 144B
#define KT_BYTES (64 * LKH * 2)       // 9216
#define OFF_K0 0
#define OFF_V0 KT_BYTES               // 9216
#define OFF_K1 (2 * KT_BYTES)         // 18432
#define OFF_V1 (3 * KT_BYTES)         // 27648
#define OFF_P  (4 * KT_BYTES)         // 36864
#define PW_BYTES (16 * LKH * 2)       // 2304
#define OFF_MD (OFF_P + 8 * PW_BYTES) // 55296
#define ATT_SMEM (OFF_MD + 512)       // 55808

__global__ __launch_bounds__(256, 2)
void attn_mma(const float* __restrict__ mask)
{
    extern __shared__ char smc[];
    const uint32_t sb = (uint32_t)__cvta_generic_to_shared(smc);
    float* madds = reinterpret_cast<float*>(smc + OFF_MD);

    const int bh = blockIdx.y;
    const int b_ = bh >> 4;
    const int h  = bh & (NH - 1);
    const int q0 = blockIdx.x * 128;
    const int tid = threadIdx.x;
    const int wid = tid >> 5;
    const int lane = tid & 31;
    const int r4 = lane >> 2;
    const int c4 = lane & 3;
    const int quad = lane >> 3;
    const int lrow = lane & 7;

    const int qrow = q0 + wid * 16;

    // Q fragments: 4 k16-steps x 4 regs (half2 pairs)
    uint32_t aq[4][4];
    {
        const uint32_t* Q32 = reinterpret_cast<const uint32_t*>(g_Q + ((size_t)bh * SS + qrow) * HD);
#pragma unroll
        for (int ks = 0; ks < 4; ks++) {
            const int base0 = r4 * 32 + ks * 8 + c4;
            const int base1 = (r4 + 8) * 32 + ks * 8 + c4;
            aq[ks][0] = Q32[base0];
            aq[ks][1] = Q32[base1];
            aq[ks][2] = Q32[base0 + 4];
            aq[ks][3] = Q32[base1 + 4];
        }
    }

    float ctx[8][4];
#pragma unroll
    for (int nt = 0; nt < 8; nt++)
#pragma unroll
        for (int i = 0; i < 4; i++) ctx[nt][i] = 0.f;
    float lp0 = 0.f, lp1 = 0.f;
    const float scale = 0.125f;

    const int krow = tid >> 2;          // 0..63
    const int kcb = (tid & 3) * 16;     // half col base

    auto stage = [&](int buf, int kt) {
        const __half* Kp = g_K + ((size_t)bh * SS + kt + krow) * HD + kcb;
        uint32_t kd = sb + (uint32_t)((buf ? OFF_K1 : OFF_K0) + krow * (LKH * 2) + kcb * 2);
        cp16(kd, Kp); cp16(kd + 16, Kp + 8);
        const __half* Vp = g_V + ((size_t)bh * HD + krow) * SS + kt + kcb;
        uint32_t vd = sb + (uint32_t)((buf ? OFF_V1 : OFF_V0) + krow * (LKH * 2) + kcb * 2);
        cp16(vd, Vp); cp16(vd + 16, Vp + 8);
        if (tid < 64)
            madds[buf * 64 + tid] = (1.0f - mask[b_ * SS + kt + tid]) * -10000.0f;
    };

    const uint32_t boffp = (uint32_t)(((quad >> 1) * 8 + lrow) * (LKH * 2) + (quad & 1) * 16);
    const uint32_t poff  = (uint32_t)(((quad & 1) * 8 + lrow) * (LKH * 2) + (quad >> 1) * 16);
    const uint32_t pwbase = sb + (uint32_t)(OFF_P + wid * PW_BYTES);
    char* Pw = smc + OFF_P + wid * PW_BYTES;

    stage(0, 0);
    cp_commit();

    const int NT = SS / 64;   // 32
    for (int t = 0; t < NT; t++) {
        const int cur = t & 1;
        cp_wait0();
        __syncthreads();
        if (t + 1 < NT) { stage(cur ^ 1, (t + 1) * 64); cp_commit(); }

        const uint32_t kb = sb + (uint32_t)(cur ? OFF_K1 : OFF_K0);
        const uint32_t vb = sb + (uint32_t)(cur ? OFF_V1 : OFF_V0);
        const float* madd = &madds[cur * 64];

        // ---- S = Q @ K^T ----
        float sf[8][4];
#pragma unroll
        for (int nt = 0; nt < 8; nt++)
            sf[nt][0] = sf[nt][1] = sf[nt][2] = sf[nt][3] = 0.f;
#pragma unroll
        for (int ks = 0; ks < 4; ks++) {
            uint32_t bf[8][2];
#pragma unroll
            for (int p = 0; p < 4; p++)
                ldsm4(bf[2 * p][0], bf[2 * p][1], bf[2 * p + 1][0], bf[2 * p + 1][1],
                      kb + boffp + (uint32_t)(p * 16 * LKH * 2) + (uint32_t)(ks * 32));
#pragma unroll
            for (int nt = 0; nt < 8; nt++)
                mma_fp16(sf[nt][0], sf[nt][1], sf[nt][2], sf[nt][3],
                         aq[ks][0], aq[ks][1], aq[ks][2], aq[ks][3],
                         bf[nt][0], bf[nt][1]);
        }

        // ---- no-max softmax: p = exp(s*scale + madd); per-thread partial sums ----
#pragma unroll
        for (int nt = 0; nt < 8; nt++) {
            float ma = madd[nt * 8 + 2 * c4];
            float mb = madd[nt * 8 + 2 * c4 + 1];
            float p0 = __expf(sf[nt][0] * scale + ma);
            float p1 = __expf(sf[nt][1] * scale + mb);
            float p2 = __expf(sf[nt][2] * scale + ma);
            float p3 = __expf(sf[nt][3] * scale + mb);
            lp0 += p0 + p1;
            lp1 += p2 + p3;
            *reinterpret_cast<uint32_t*>(Pw + (r4 * LKH + nt * 8 + 2 * c4) * 2) = cvt_h2(p0, p1);
            *reinterpret_cast<uint32_t*>(Pw + ((r4 + 8) * LKH + nt * 8 + 2 * c4) * 2) = cvt_h2(p2, p3);
        }
        __syncwarp();

        // ---- ctx += P @ V ----
#pragma unroll
        for (int ks2 = 0; ks2 < 4; ks2++) {
            uint32_t ap0, ap1, ap2, ap3;
            ldsm4(ap0, ap1, ap2, ap3, pwbase + poff + (uint32_t)(ks2 * 32));
            uint32_t vf[8][2];
#pragma unroll
            for (int p = 0; p < 4; p++)
                ldsm4(vf[2 * p][0], vf[2 * p][1], vf[2 * p + 1][0], vf[2 * p + 1][1],
                      vb + boffp + (uint32_t)(p * 16 * LKH * 2) + (uint32_t)(ks2 * 32));
#pragma unroll
            for (int nt2 = 0; nt2 < 8; nt2++)
                mma_fp16(ctx[nt2][0], ctx[nt2][1], ctx[nt2][2], ctx[nt2][3],
                         ap0, ap1, ap2, ap3, vf[nt2][0], vf[nt2][1]);
        }
        __syncwarp();
    }

    // ---- final denominator reduction + epilogue (fp16 ctx out) ----
    lp0 += __shfl_xor_sync(0xffffffff, lp0, 1);
    lp0 += __shfl_xor_sync(0xffffffff, lp0, 2);
    lp1 += __shfl_xor_sync(0xffffffff, lp1, 1);
    lp1 += __shfl_xor_sync(0xffffffff, lp1, 2);
    float inv0 = 1.0f / lp0;
    float inv1 = 1.0f / lp1;
    const int sq0 = qrow + r4;
    __half* C0 = g_ctx + ((size_t)(b_ * SS + sq0) * EDIM) + h * HD;
    __half* C1 = g_ctx + ((size_t)(b_ * SS + sq0 + 8) * EDIM) + h * HD;
#pragma unroll
    for (int nt2 = 0; nt2 < 8; nt2++) {
        const int col = nt2 * 8 + 2 * c4;
        *reinterpret_cast<uint32_t*>(&C0[col]) = cvt_h2(ctx[nt2][0] * inv0, ctx[nt2][1] * inv0);
        *reinterpret_cast<uint32_t*>(&C1[col]) = cvt_h2(ctx[nt2][2] * inv1, ctx[nt2][3] * inv1);
    }
}

// ============================ launch ============================
extern "C" void kernel_launch(void* const* d_in, const int* in_sizes, int n_in,
                              void* d_out, int out_size)
{
    const float* X    = (const float*)d_in[0];
    const float* mask = (const float*)d_in[1];
    const float* Wq   = (const float*)d_in[2];
    const float* bq   = (const float*)d_in[3];
    const float* Wk   = (const float*)d_in[4];
    const float* bk   = (const float*)d_in[5];
    const float* Wv   = (const float*)d_in[6];
    const float* bv   = (const float*)d_in[7];
    const float* Wo   = (const float*)d_in[8];
    const float* bo   = (const float*)d_in[9];
    float* out = (float*)d_out;

    cudaFuncSetAttribute(gemm_qkv, cudaFuncAttributeMaxDynamicSharedMemorySize, GEMM_SMEM);
    cudaFuncSetAttribute(gemm_out, cudaFuncAttributeMaxDynamicSharedMemorySize, GEMM_SMEM);
    cudaFuncSetAttribute(attn_mma, cudaFuncAttributeMaxDynamicSharedMemorySize, ATT_SMEM);

    prep_x<<<MTOT * EDIM / 1024, 256>>>(X);

    dim3 tgrid(32, 32, 4), tblk(32, 8);
    transpose4<<<tgrid, tblk>>>(Wq, Wk, Wv, Wo);

    dim3 qkvgrid(MTOT / GBM, EDIM / GBN, 3);   // 32 x 8 x 3
    gemm_qkv<<<qkvgrid, 256, GEMM_SMEM>>>(bq, bk, bv);

    dim3 agrid(SS / 128, BB * NH);             // 16 x 32
    attn_mma<<<agrid, 256, ATT_SMEM>>>(mask);

    dim3 ogrid(MTOT / GBM, EDIM / GBN);        // 32 x 8
    gemm_out<<<ogrid, 256, GEMM_SMEM>>>(bo, out);
}

// round 15
// speedup vs baseline: 3.0965x; 1.0969x over previous
#include <cuda_runtime.h>
#include <cuda_fp16.h>
#include <math.h>
#include <cstdint>

#define EDIM 1024
#define NH   16
#define HD   64
#define BB   2
#define SS   2048
#define MTOT (BB*SS)   // 4096

#define QSCALE 0.180336880f   // 0.125 * log2(e)
#define MSCALE 1.44269504f    // log2(e)

// Scratch (fp16)
__device__ __half g_Xt[MTOT*EDIM];
__device__ __half g_Q[MTOT*EDIM];     // pre-scaled by QSCALE
__device__ __half g_K[MTOT*EDIM];
__device__ __half g_V[MTOT*EDIM];     // TRANSPOSED: [b][h][d][s]
__device__ __half g_ctx[MTOT*EDIM];
__device__ __half g_Wt[4][EDIM*EDIM]; // transposed weights [n][k]

// pack two floats -> half2 (lo in low half)
__device__ __forceinline__ uint32_t cvt_h2(float lo, float hi) {
    uint32_t r; asm("cvt.rn.f16x2.f32 %0,%1,%2;" : "=r"(r) : "f"(hi), "f"(lo));
    return r;
}
__device__ __forceinline__ float ex2f(float x) {
    float r; asm("ex2.approx.f32 %0,%1;" : "=f"(r) : "f"(x));
    return r;
}
__device__ __forceinline__ void mma_fp16(float& d0, float& d1, float& d2, float& d3,
                                         uint32_t a0, uint32_t a1, uint32_t a2, uint32_t a3,
                                         uint32_t b0, uint32_t b1) {
    asm volatile(
        "mma.sync.aligned.m16n8k16.row.col.f32.f16.f16.f32 "
        "{%0,%1,%2,%3},{%4,%5,%6,%7},{%8,%9},{%0,%1,%2,%3};"
        : "+f"(d0), "+f"(d1), "+f"(d2), "+f"(d3)
        : "r"(a0), "r"(a1), "r"(a2), "r"(a3), "r"(b0), "r"(b1));
}
__device__ __forceinline__ void ldsm4(uint32_t& r0, uint32_t& r1, uint32_t& r2, uint32_t& r3,
                                      uint32_t addr) {
    asm volatile("ldmatrix.sync.aligned.m8n8.x4.shared.b16 {%0,%1,%2,%3}, [%4];"
                 : "=r"(r0), "=r"(r1), "=r"(r2), "=r"(r3) : "r"(addr));
}
__device__ __forceinline__ void cp16(uint32_t dst, const void* src) {
    asm volatile("cp.async.cg.shared.global [%0], [%1], 16;" :: "r"(dst), "l"(src));
}
__device__ __forceinline__ void cp_commit() { asm volatile("cp.async.commit_group;"); }
__device__ __forceinline__ void cp_wait0()  { asm volatile("cp.async.wait_group 0;" ::: "memory"); }

// ============================ X -> fp16 prep ============================
__global__ __launch_bounds__(256)
void prep_x(const float* __restrict__ X)
{
    size_t i = ((size_t)blockIdx.x * 256 + threadIdx.x) * 4;
    float4 v = *reinterpret_cast<const float4*>(&X[i]);
    uint2 o;
    o.x = cvt_h2(v.x, v.y);
    o.y = cvt_h2(v.z, v.w);
    *reinterpret_cast<uint2*>(&g_Xt[i]) = o;
}

// ============================ fused transpose (fp16 out) ============================
__global__ __launch_bounds__(256)
void transpose4(const float* __restrict__ w0, const float* __restrict__ w1,
                const float* __restrict__ w2, const float* __restrict__ w3)
{
    const float* in = (blockIdx.z == 0) ? w0 : (blockIdx.z == 1) ? w1 : (blockIdx.z == 2) ? w2 : w3;
    __half* out = g_Wt[blockIdx.z];
    __shared__ float t[32][33];
    int x = blockIdx.x * 32 + threadIdx.x;
    int y = blockIdx.y * 32 + threadIdx.y;
#pragma unroll
    for (int j = 0; j < 32; j += 8)
        t[threadIdx.y + j][threadIdx.x] = in[(size_t)(y + j) * EDIM + x];
    __syncthreads();
    x = blockIdx.y * 32 + threadIdx.x;
    y = blockIdx.x * 32 + threadIdx.y;
#pragma unroll
    for (int j = 0; j < 32; j += 8)
        out[(size_t)(y + j) * EDIM + x] = __float2half_rn(t[threadIdx.x][threadIdx.y + j]);
}

// ============================ fp16 mma.sync GEMM ============================
#define GBM 128
#define GBN 128
#define GBK 32
#define LDA 40                       // halves per SMEM row (32 data + 8 pad) = 80B
#define TILE_BYTES (128 * LDA * 2)   // 10240
#define GEMM_SMEM (4 * TILE_BYTES)   // 40960

// out_mode: 0 = float row-major; 1 = fp16 [b][h][s][d]; 2 = fp16 [b][h][d][s]
__device__ __forceinline__ void gemm_body(const __half* __restrict__ A,
                                          const __half* __restrict__ Wt,
                                          const float* __restrict__ bias,
                                          void* __restrict__ Cv,
                                          int out_mode, float oscale, int m0, int n0)
{
    extern __shared__ char smc[];
    const uint32_t sb = (uint32_t)__cvta_generic_to_shared(smc);

    const int tid = threadIdx.x;
    const int wid = tid >> 5;
    const int lane = tid & 31;
    const int warp_m = (wid & 3) * 32;
    const int warp_n = (wid >> 2) * 64;
    const int r4 = lane >> 2;
    const int c4 = lane & 3;
    const int quad = lane >> 3;
    const int lrow = lane & 7;

    float acc[2][8][4];
#pragma unroll
    for (int mt = 0; mt < 2; mt++)
#pragma unroll
        for (int nt = 0; nt < 8; nt++)
#pragma unroll
            for (int i = 0; i < 4; i++) acc[mt][nt][i] = 0.f;

    const int sr = tid >> 1;             // row 0..127
    const int sch = (tid & 1) * 16;      // half col base
    auto stage = [&](int buf, int k0) {
        uint32_t ad = sb + (uint32_t)(buf * 2 * TILE_BYTES + sr * (LDA * 2) + sch * 2);
        const __half* Ap = &A[(size_t)(m0 + sr) * EDIM + k0 + sch];
        cp16(ad, Ap); cp16(ad + 16, Ap + 8);
        uint32_t bd = ad + (uint32_t)TILE_BYTES;
        const __half* Bp = &Wt[(size_t)(n0 + sr) * EDIM + k0 + sch];
        cp16(bd, Bp); cp16(bd + 16, Bp + 8);
    };

    const uint32_t aoff = (uint32_t)(((warp_m + (quad & 1) * 8 + lrow) * LDA + (quad >> 1) * 8) * 2);
    const uint32_t boff = (uint32_t)(((warp_n + (quad >> 1) * 8 + lrow) * LDA + (quad & 1) * 8) * 2);

    stage(0, 0);
    cp_commit();

    const int NCHUNK = EDIM / GBK;   // 32
    for (int c = 0; c < NCHUNK; c++) {
        const int cur = c & 1;
        cp_wait0();
        __syncthreads();
        if (c + 1 < NCHUNK) { stage(cur ^ 1, (c + 1) * GBK); cp_commit(); }

        const uint32_t ab = sb + (uint32_t)(cur * 2 * TILE_BYTES);
        const uint32_t bb = ab + (uint32_t)TILE_BYTES;
#pragma unroll
        for (int ks = 0; ks < 2; ks++) {
            const uint32_t kbb = (uint32_t)(ks * 32);   // 16 halves
            uint32_t af[2][4];
#pragma unroll
            for (int mt = 0; mt < 2; mt++)
                ldsm4(af[mt][0], af[mt][1], af[mt][2], af[mt][3],
                      ab + aoff + (uint32_t)(mt * 16 * LDA * 2) + kbb);
            uint32_t bf[8][2];
#pragma unroll
            for (int p = 0; p < 4; p++)
                ldsm4(bf[2 * p][0], bf[2 * p][1], bf[2 * p + 1][0], bf[2 * p + 1][1],
                      bb + boff + (uint32_t)(p * 16 * LDA * 2) + kbb);
#pragma unroll
            for (int mt = 0; mt < 2; mt++)
#pragma unroll
                for (int nt = 0; nt < 8; nt++)
                    mma_fp16(acc[mt][nt][0], acc[mt][nt][1], acc[mt][nt][2], acc[mt][nt][3],
                             af[mt][0], af[mt][1], af[mt][2], af[mt][3],
                             bf[nt][0], bf[nt][1]);
        }
    }

    // ---- epilogue ----
#pragma unroll
    for (int mt = 0; mt < 2; mt++) {
#pragma unroll
        for (int half = 0; half < 2; half++) {
            const int m = m0 + warp_m + mt * 16 + r4 + half * 8;
            const int b_ = m >> 11;
            const int s_ = m & (SS - 1);
#pragma unroll
            for (int nt = 0; nt < 8; nt++) {
                const int col = warp_n + n0 + nt * 8 + 2 * c4;
                float ox = (acc[mt][nt][half * 2 + 0] + bias[col]) * oscale;
                float oy = (acc[mt][nt][half * 2 + 1] + bias[col + 1]) * oscale;
                if (out_mode == 1) {
                    const int h = col >> 6;
                    const int d = col & (HD - 1);
                    __half* C = (__half*)Cv;
                    *reinterpret_cast<uint32_t*>(
                        &C[(((size_t)(b_ * NH + h) * SS + s_) * HD) + d]) = cvt_h2(ox, oy);
                } else if (out_mode == 2) {
                    const int h = col >> 6;
                    const int d = col & (HD - 1);
                    __half* C = (__half*)Cv;
                    C[((size_t)(b_ * NH + h) * HD + d) * SS + s_]     = __float2half_rn(ox);
                    C[((size_t)(b_ * NH + h) * HD + d + 1) * SS + s_] = __float2half_rn(oy);
                } else {
                    float* C = (float*)Cv;
                    *reinterpret_cast<float2*>(&C[(size_t)m * EDIM + col]) = make_float2(ox, oy);
                }
            }
        }
    }
}

__global__ __launch_bounds__(256, 2)
void gemm_qkv(const float* __restrict__ bq, const float* __restrict__ bk,
              const float* __restrict__ bv)
{
    const int z = blockIdx.z;
    const float* bias = (z == 0) ? bq : (z == 1) ? bk : bv;
    __half* C = (z == 0) ? g_Q : (z == 1) ? g_K : g_V;
    const float osc = (z == 0) ? QSCALE : 1.0f;
    gemm_body(g_Xt, g_Wt[z], bias, C, (z == 2) ? 2 : 1, osc, blockIdx.x * GBM, blockIdx.y * GBN);
}

__global__ __launch_bounds__(256, 2)
void gemm_out(const float* __restrict__ bo, float* __restrict__ C)
{
    gemm_body(g_ctx, g_Wt[3], bo, C, 0, 1.0f, blockIdx.x * GBM, blockIdx.y * GBN);
}

// ============================ flash attention fp16: register P, 2 CTAs/SM ============================
#define LKH 72                        // halves per SMEM row (64 + 8 pad) = 144B
#define KT_BYTES (64 * LKH * 2)       // 9216
#define OFF_K0 0
#define OFF_V0 KT_BYTES               // 9216
#define OFF_K1 (2 * KT_BYTES)         // 18432
#define OFF_V1 (3 * KT_BYTES)         // 27648
#define OFF_MD (4 * KT_BYTES)         // 36864
#define ATT_SMEM (OFF_MD + 512)       // 37376

__global__ __launch_bounds__(256, 2)
void attn_mma(const float* __restrict__ mask)
{
    extern __shared__ char smc[];
    const uint32_t sb = (uint32_t)__cvta_generic_to_shared(smc);
    float* madds = reinterpret_cast<float*>(smc + OFF_MD);

    const int bh = blockIdx.y;
    const int b_ = bh >> 4;
    const int h  = bh & (NH - 1);
    const int q0 = blockIdx.x * 128;
    const int tid = threadIdx.x;
    const int wid = tid >> 5;
    const int lane = tid & 31;
    const int r4 = lane >> 2;
    const int c4 = lane & 3;
    const int quad = lane >> 3;
    const int lrow = lane & 7;

    const int qrow = q0 + wid * 16;

    // Q fragments (pre-scaled by QSCALE at projection time)
    uint32_t aq[4][4];
    {
        const uint32_t* Q32 = reinterpret_cast<const uint32_t*>(g_Q + ((size_t)bh * SS + qrow) * HD);
#pragma unroll
        for (int ks = 0; ks < 4; ks++) {
            const int base0 = r4 * 32 + ks * 8 + c4;
            const int base1 = (r4 + 8) * 32 + ks * 8 + c4;
            aq[ks][0] = Q32[base0];
            aq[ks][1] = Q32[base1];
            aq[ks][2] = Q32[base0 + 4];
            aq[ks][3] = Q32[base1 + 4];
        }
    }

    float ctx[8][4];
#pragma unroll
    for (int nt = 0; nt < 8; nt++)
#pragma unroll
        for (int i = 0; i < 4; i++) ctx[nt][i] = 0.f;
    float lp0 = 0.f, lp1 = 0.f;

    const int krow = tid >> 2;          // 0..63
    const int kcb = (tid & 3) * 16;     // half col base

    auto stage = [&](int buf, int kt) {
        const __half* Kp = g_K + ((size_t)bh * SS + kt + krow) * HD + kcb;
        uint32_t kd = sb + (uint32_t)((buf ? OFF_K1 : OFF_K0) + krow * (LKH * 2) + kcb * 2);
        cp16(kd, Kp); cp16(kd + 16, Kp + 8);
        const __half* Vp = g_V + ((size_t)bh * HD + krow) * SS + kt + kcb;
        uint32_t vd = sb + (uint32_t)((buf ? OFF_V1 : OFF_V0) + krow * (LKH * 2) + kcb * 2);
        cp16(vd, Vp); cp16(vd + 16, Vp + 8);
        if (tid < 64)
            madds[buf * 64 + tid] = (1.0f - mask[b_ * SS + kt + tid]) * -10000.0f * MSCALE;
    };

    const uint32_t boffp = (uint32_t)(((quad >> 1) * 8 + lrow) * (LKH * 2) + (quad & 1) * 16);

    stage(0, 0);
    cp_commit();

    const int NT = SS / 64;   // 32
    for (int t = 0; t < NT; t++) {
        const int cur = t & 1;
        cp_wait0();
        __syncthreads();
        if (t + 1 < NT) { stage(cur ^ 1, (t + 1) * 64); cp_commit(); }

        const uint32_t kb = sb + (uint32_t)(cur ? OFF_K1 : OFF_K0);
        const uint32_t vb = sb + (uint32_t)(cur ? OFF_V1 : OFF_V0);
        const float* madd = &madds[cur * 64];

        // ---- S' = (Q*QSCALE) @ K^T  (log2-domain scores) ----
        float sf[8][4];
#pragma unroll
        for (int nt = 0; nt < 8; nt++)
            sf[nt][0] = sf[nt][1] = sf[nt][2] = sf[nt][3] = 0.f;
#pragma unroll
        for (int ks = 0; ks < 4; ks++) {
            uint32_t bf[8][2];
#pragma unroll
            for (int p = 0; p < 4; p++)
                ldsm4(bf[2 * p][0], bf[2 * p][1], bf[2 * p + 1][0], bf[2 * p + 1][1],
                      kb + boffp + (uint32_t)(p * 16 * LKH * 2) + (uint32_t)(ks * 32));
#pragma unroll
            for (int nt = 0; nt < 8; nt++)
                mma_fp16(sf[nt][0], sf[nt][1], sf[nt][2], sf[nt][3],
                         aq[ks][0], aq[ks][1], aq[ks][2], aq[ks][3],
                         bf[nt][0], bf[nt][1]);
        }

        // ---- softmax: p = 2^(s' + madd'); P stays in registers as PV A-fragments ----
        uint32_t p2a[8], p2b[8];
#pragma unroll
        for (int nt = 0; nt < 8; nt++) {
            float2 mm = *reinterpret_cast<const float2*>(&madd[nt * 8 + 2 * c4]);
            float e0 = ex2f(sf[nt][0] + mm.x);
            float e1 = ex2f(sf[nt][1] + mm.y);
            float e2 = ex2f(sf[nt][2] + mm.x);
            float e3 = ex2f(sf[nt][3] + mm.y);
            lp0 += e0 + e1;
            lp1 += e2 + e3;
            p2a[nt] = cvt_h2(e0, e1);   // row r4
            p2b[nt] = cvt_h2(e2, e3);   // row r4+8
        }

        // ---- ctx += P @ V  (P A-fragments direct from registers) ----
#pragma unroll
        for (int ks2 = 0; ks2 < 4; ks2++) {
            uint32_t ap0 = p2a[2 * ks2];
            uint32_t ap1 = p2b[2 * ks2];
            uint32_t ap2 = p2a[2 * ks2 + 1];
            uint32_t ap3 = p2b[2 * ks2 + 1];
            uint32_t vf[8][2];
#pragma unroll
            for (int p = 0; p < 4; p++)
                ldsm4(vf[2 * p][0], vf[2 * p][1], vf[2 * p + 1][0], vf[2 * p + 1][1],
                      vb + boffp + (uint32_t)(p * 16 * LKH * 2) + (uint32_t)(ks2 * 32));
#pragma unroll
            for (int nt2 = 0; nt2 < 8; nt2++)
                mma_fp16(ctx[nt2][0], ctx[nt2][1], ctx[nt2][2], ctx[nt2][3],
                         ap0, ap1, ap2, ap3, vf[nt2][0], vf[nt2][1]);
        }
    }

    // ---- final denominator reduction + epilogue (fp16 ctx out) ----
    lp0 += __shfl_xor_sync(0xffffffff, lp0, 1);
    lp0 += __shfl_xor_sync(0xffffffff, lp0, 2);
    lp1 += __shfl_xor_sync(0xffffffff, lp1, 1);
    lp1 += __shfl_xor_sync(0xffffffff, lp1, 2);
    float inv0 = 1.0f / lp0;
    float inv1 = 1.0f / lp1;
    const int sq0 = qrow + r4;
    __half* C0 = g_ctx + ((size_t)(b_ * SS + sq0) * EDIM) + h * HD;
    __half* C1 = g_ctx + ((size_t)(b_ * SS + sq0 + 8) * EDIM) + h * HD;
#pragma unroll
    for (int nt2 = 0; nt2 < 8; nt2++) {
        const int col = nt2 * 8 + 2 * c4;
        *reinterpret_cast<uint32_t*>(&C0[col]) = cvt_h2(ctx[nt2][0] * inv0, ctx[nt2][1] * inv0);
        *reinterpret_cast<uint32_t*>(&C1[col]) = cvt_h2(ctx[nt2][2] * inv1, ctx[nt2][3] * inv1);
    }
}

// ============================ launch ============================
extern "C" void kernel_launch(void* const* d_in, const int* in_sizes, int n_in,
                              void* d_out, int out_size)
{
    const float* X    = (const float*)d_in[0];
    const float* mask = (const float*)d_in[1];
    const float* Wq   = (const float*)d_in[2];
    const float* bq   = (const float*)d_in[3];
    const float* Wk   = (const float*)d_in[4];
    const float* bk   = (const float*)d_in[5];
    const float* Wv   = (const float*)d_in[6];
    const float* bv   = (const float*)d_in[7];
    const float* Wo   = (const float*)d_in[8];
    const float* bo   = (const float*)d_in[9];
    float* out = (float*)d_out;

    cudaFuncSetAttribute(gemm_qkv, cudaFuncAttributeMaxDynamicSharedMemorySize, GEMM_SMEM);
    cudaFuncSetAttribute(gemm_out, cudaFuncAttributeMaxDynamicSharedMemorySize, GEMM_SMEM);
    cudaFuncSetAttribute(attn_mma, cudaFuncAttributeMaxDynamicSharedMemorySize, ATT_SMEM);

    prep_x<<<MTOT * EDIM / 1024, 256>>>(X);

    dim3 tgrid(32, 32, 4), tblk(32, 8);
    transpose4<<<tgrid, tblk>>>(Wq, Wk, Wv, Wo);

    dim3 qkvgrid(MTOT / GBM, EDIM / GBN, 3);   // 32 x 8 x 3
    gemm_qkv<<<qkvgrid, 256, GEMM_SMEM>>>(bq, bk, bv);

    dim3 agrid(SS / 128, BB * NH);             // 16 x 32
    attn_mma<<<agrid, 256, ATT_SMEM>>>(mask);

    dim3 ogrid(MTOT / GBM, EDIM / GBN);        // 32 x 8
    gemm_out<<<ogrid, 256, GEMM_SMEM>>>(bo, out);
}